// round 1
// baseline (speedup 1.0000x reference)
#include <cuda_runtime.h>
#include <cstdint>

#define NN 50000
#define EE 800000
#define IN_F 128
#define HC 256
#define NHEAD 8
#define CDIM 32
#define GG 64
#define OUTF 64
#define NLAYERS 4

// ---------------- scratch (device globals; no allocation allowed) ----------------
__device__ float g_q[(size_t)NN * HC];
__device__ float g_k[(size_t)NN * HC];
__device__ float g_v[(size_t)NN * HC];
__device__ float g_skip[(size_t)NN * HC];
__device__ float g_h[(size_t)NN * HC];
__device__ int   g_deg[NN];
__device__ int   g_rowptr[NN + 1];
__device__ int   g_cursor[NN];
__device__ int   g_csrsrc[EE];
__device__ float g_pooled[GG * HC];
__device__ int   g_gcnt[GG];

// ---------------- small utility kernels ----------------
__global__ void zero_i_kernel(int* p, int n) {
    int i = blockIdx.x * blockDim.x + threadIdx.x;
    if (i < n) p[i] = 0;
}
__global__ void zero_f_kernel(float* p, int n) {
    int i = blockIdx.x * blockDim.x + threadIdx.x;
    if (i < n) p[i] = 0.0f;
}

// ---------------- CSR build ----------------
__global__ void hist_kernel(const int* __restrict__ dst, int* __restrict__ deg, int e) {
    int i = blockIdx.x * blockDim.x + threadIdx.x;
    if (i < e) atomicAdd(&deg[dst[i]], 1);
}

__global__ void scan_kernel(const int* __restrict__ deg, int* __restrict__ rowptr, int n) {
    __shared__ int sh[1024];
    __shared__ int carry;
    int tid = threadIdx.x;
    if (tid == 0) { carry = 0; rowptr[0] = 0; }
    __syncthreads();
    for (int base = 0; base < n; base += 1024) {
        int i = base + tid;
        sh[tid] = (i < n) ? deg[i] : 0;
        __syncthreads();
        for (int off = 1; off < 1024; off <<= 1) {
            int t = (tid >= off) ? sh[tid - off] : 0;
            __syncthreads();
            sh[tid] += t;
            __syncthreads();
        }
        int c = carry;
        if (i < n) rowptr[i + 1] = sh[tid] + c;
        __syncthreads();
        if (tid == 0) carry = c + sh[1023];
        __syncthreads();
    }
}

__global__ void cursor_init_kernel(const int* __restrict__ rowptr, int* __restrict__ cur, int n) {
    int i = blockIdx.x * blockDim.x + threadIdx.x;
    if (i < n) cur[i] = rowptr[i];
}

__global__ void scatter_kernel(const int* __restrict__ src, const int* __restrict__ dst,
                               int* __restrict__ cur, int* __restrict__ csrsrc, int e) {
    int i = blockIdx.x * blockDim.x + threadIdx.x;
    if (i < e) {
        int d = dst[i];
        int pos = atomicAdd(&cur[d], 1);
        csrsrc[pos] = src[i];
    }
}

// ---------------- GEMM: C[M,256] = A[M,K] @ W[K,256] + b (4 matrices per launch) ----------------
struct GemmPtrs {
    const float* W[4];
    const float* b[4];
    float* C[4];
};

#define BM 128
#define BN 64
#define BK 16

__global__ __launch_bounds__(256) void gemm4_kernel(const float* __restrict__ A, int K,
                                                    GemmPtrs P, int M) {
    const float* __restrict__ W = P.W[blockIdx.z];
    const float* __restrict__ bias = P.b[blockIdx.z];
    float* __restrict__ C = P.C[blockIdx.z];

    __shared__ float As[BK][BM];
    __shared__ float Bs[BK][BN];

    int t = threadIdx.x;           // 0..255
    int tx = t & 15;               // n sub-tile
    int ty = t >> 4;               // m sub-tile
    int m0 = blockIdx.x * BM;
    int n0 = blockIdx.y * BN;

    float acc[8][4];
#pragma unroll
    for (int i = 0; i < 8; i++)
#pragma unroll
        for (int j = 0; j < 4; j++) acc[i][j] = 0.0f;

    for (int k0 = 0; k0 < K; k0 += BK) {
        // load A tile (BM x BK) transposed into As[k][m]
#pragma unroll
        for (int u = 0; u < 2; u++) {
            int f = t + u * 256;      // 0..511 float4 slots
            int r = f >> 2;           // row 0..127
            int c4 = f & 3;           // col group 0..3
            float4 av = make_float4(0.f, 0.f, 0.f, 0.f);
            int gm = m0 + r;
            if (gm < M) av = *(const float4*)(A + (size_t)gm * K + k0 + c4 * 4);
            As[c4 * 4 + 0][r] = av.x;
            As[c4 * 4 + 1][r] = av.y;
            As[c4 * 4 + 2][r] = av.z;
            As[c4 * 4 + 3][r] = av.w;
        }
        // load B tile (BK x BN)
        {
            int kr = t >> 4;   // 0..15
            int c4 = t & 15;   // 0..15
            float4 bv = *(const float4*)(W + (size_t)(k0 + kr) * HC + n0 + c4 * 4);
            *(float4*)&Bs[kr][c4 * 4] = bv;
        }
        __syncthreads();
#pragma unroll
        for (int kk = 0; kk < BK; kk++) {
            float a[8], bb[4];
#pragma unroll
            for (int i = 0; i < 8; i++) a[i] = As[kk][ty * 8 + i];
#pragma unroll
            for (int j = 0; j < 4; j++) bb[j] = Bs[kk][tx * 4 + j];
#pragma unroll
            for (int i = 0; i < 8; i++)
#pragma unroll
                for (int j = 0; j < 4; j++) acc[i][j] += a[i] * bb[j];
        }
        __syncthreads();
    }

    float bl[4];
#pragma unroll
    for (int j = 0; j < 4; j++) bl[j] = bias[n0 + tx * 4 + j];
#pragma unroll
    for (int i = 0; i < 8; i++) {
        int gm = m0 + ty * 8 + i;
        if (gm < M) {
            float4 ov;
            ov.x = acc[i][0] + bl[0];
            ov.y = acc[i][1] + bl[1];
            ov.z = acc[i][2] + bl[2];
            ov.w = acc[i][3] + bl[3];
            *(float4*)(C + (size_t)gm * HC + n0 + tx * 4) = ov;
        }
    }
}

// ---------------- attention: one warp per dst node, streaming softmax ----------------
__global__ __launch_bounds__(256) void attn_kernel(
    const float* __restrict__ q, const float* __restrict__ k,
    const float* __restrict__ v, const float* __restrict__ skp,
    const int* __restrict__ rowptr, const int* __restrict__ srcs,
    float* __restrict__ hout, int n_nodes) {

    int warp = (blockIdx.x * blockDim.x + threadIdx.x) >> 5;
    int lane = threadIdx.x & 31;
    if (warp >= n_nodes) return;

    // lane l owns channels [8l, 8l+8) -> head l/4
    const float4* qp = (const float4*)(q + (size_t)warp * HC);
    float4 q1 = qp[lane * 2];
    float4 q2 = qp[lane * 2 + 1];

    float m = -1e30f;
    float ssum = 0.0f;
    float acc0 = 0.f, acc1 = 0.f, acc2 = 0.f, acc3 = 0.f;
    float acc4 = 0.f, acc5 = 0.f, acc6 = 0.f, acc7 = 0.f;

    const float scale = 0.17677669529663687f;  // 1/sqrt(32)

    int e0 = rowptr[warp];
    int e1 = rowptr[warp + 1];
    for (int e = e0; e < e1; e++) {
        int s = srcs[e];
        const float4* kp = (const float4*)(k + (size_t)s * HC);
        float4 k1 = kp[lane * 2];
        float4 k2 = kp[lane * 2 + 1];
        float d = q1.x * k1.x + q1.y * k1.y + q1.z * k1.z + q1.w * k1.w +
                  q2.x * k2.x + q2.y * k2.y + q2.z * k2.z + q2.w * k2.w;
        d += __shfl_xor_sync(0xffffffffu, d, 1);
        d += __shfl_xor_sync(0xffffffffu, d, 2);
        float logit = d * scale;
        float mn = fmaxf(m, logit);
        float corr = __expf(m - mn);
        float p = __expf(logit - mn);
        m = mn;
        ssum = ssum * corr + p;
        const float4* vp = (const float4*)(v + (size_t)s * HC);
        float4 v1 = vp[lane * 2];
        float4 v2 = vp[lane * 2 + 1];
        acc0 = acc0 * corr + p * v1.x;
        acc1 = acc1 * corr + p * v1.y;
        acc2 = acc2 * corr + p * v1.z;
        acc3 = acc3 * corr + p * v1.w;
        acc4 = acc4 * corr + p * v2.x;
        acc5 = acc5 * corr + p * v2.y;
        acc6 = acc6 * corr + p * v2.z;
        acc7 = acc7 * corr + p * v2.w;
    }
    float inv = 1.0f / (ssum + 1e-16f);
    const float4* sp = (const float4*)(skp + (size_t)warp * HC);
    float4 s1 = sp[lane * 2];
    float4 s2 = sp[lane * 2 + 1];
    float4 o1, o2;
    o1.x = fmaxf(acc0 * inv + s1.x, 0.f);
    o1.y = fmaxf(acc1 * inv + s1.y, 0.f);
    o1.z = fmaxf(acc2 * inv + s1.z, 0.f);
    o1.w = fmaxf(acc3 * inv + s1.w, 0.f);
    o2.x = fmaxf(acc4 * inv + s2.x, 0.f);
    o2.y = fmaxf(acc5 * inv + s2.y, 0.f);
    o2.z = fmaxf(acc6 * inv + s2.z, 0.f);
    o2.w = fmaxf(acc7 * inv + s2.w, 0.f);
    float4* op = (float4*)(hout + (size_t)warp * HC);
    op[lane * 2] = o1;
    op[lane * 2 + 1] = o2;
}

// ---------------- pooling + FC ----------------
__global__ void pool_cnt_kernel(const int* __restrict__ batch, int* __restrict__ cnt, int n) {
    int i = blockIdx.x * blockDim.x + threadIdx.x;
    if (i < n) atomicAdd(&cnt[batch[i]], 1);
}

__global__ void pool_sum_kernel(const float* __restrict__ h, const int* __restrict__ batch,
                                float* __restrict__ pooled, int n) {
    int tid = blockIdx.x * blockDim.x + threadIdx.x;
    if (tid >= n * 64) return;
    int node = tid >> 6;
    int c4 = tid & 63;
    int g = batch[node];
    float4 hv = *(const float4*)(h + (size_t)node * HC + c4 * 4);
    atomicAdd(&pooled[g * HC + c4 * 4 + 0], hv.x);
    atomicAdd(&pooled[g * HC + c4 * 4 + 1], hv.y);
    atomicAdd(&pooled[g * HC + c4 * 4 + 2], hv.z);
    atomicAdd(&pooled[g * HC + c4 * 4 + 3], hv.w);
}

__global__ void fc_kernel(const float* __restrict__ pooled, const int* __restrict__ cnt,
                          const float* __restrict__ Wfc, const float* __restrict__ bfc,
                          float* __restrict__ out) {
    int g = blockIdx.x;
    int o = threadIdx.x;  // 64
    __shared__ float pr[HC];
    float invc = 1.0f / fmaxf((float)cnt[g], 1.0f);
    for (int c = o; c < HC; c += 64) pr[c] = pooled[g * HC + c] * invc;
    __syncthreads();
    float accu = bfc[o];
#pragma unroll 8
    for (int c = 0; c < HC; c++) accu += pr[c] * Wfc[c * OUTF + o];
    out[g * OUTF + o] = accu;
}

// ---------------- host orchestration ----------------
extern "C" void kernel_launch(void* const* d_in, const int* in_sizes, int n_in,
                              void* d_out, int out_size) {
    const float* x = (const float*)d_in[0];
    const int* edge = (const int*)d_in[1];   // [2,E]: row0=src, row1=dst
    const int* batch = (const int*)d_in[2];
    const float* Wq0 = (const float*)d_in[3];
    const float* bq0 = (const float*)d_in[4];
    const float* Wk0 = (const float*)d_in[5];
    const float* bk0 = (const float*)d_in[6];
    const float* Wv0 = (const float*)d_in[7];
    const float* bv0 = (const float*)d_in[8];
    const float* Ws0 = (const float*)d_in[9];
    const float* bs0 = (const float*)d_in[10];
    const float* Wq = (const float*)d_in[11];  // [3,256,256]
    const float* bq = (const float*)d_in[12];
    const float* Wk = (const float*)d_in[13];
    const float* bk = (const float*)d_in[14];
    const float* Wv = (const float*)d_in[15];
    const float* bv = (const float*)d_in[16];
    const float* Ws = (const float*)d_in[17];
    const float* bs = (const float*)d_in[18];
    const float* Wfc = (const float*)d_in[19];
    const float* bfc = (const float*)d_in[20];
    float* out = (float*)d_out;

    const int* srcp = edge;
    const int* dstp = edge + EE;

    // resolve device symbol addresses (host side, no alloc)
    float *q_p, *k_p, *v_p, *skip_p, *h_p, *pooled_p;
    int *deg_p, *rowptr_p, *cursor_p, *csrsrc_p, *gcnt_p;
    cudaGetSymbolAddress((void**)&q_p, g_q);
    cudaGetSymbolAddress((void**)&k_p, g_k);
    cudaGetSymbolAddress((void**)&v_p, g_v);
    cudaGetSymbolAddress((void**)&skip_p, g_skip);
    cudaGetSymbolAddress((void**)&h_p, g_h);
    cudaGetSymbolAddress((void**)&deg_p, g_deg);
    cudaGetSymbolAddress((void**)&rowptr_p, g_rowptr);
    cudaGetSymbolAddress((void**)&cursor_p, g_cursor);
    cudaGetSymbolAddress((void**)&csrsrc_p, g_csrsrc);
    cudaGetSymbolAddress((void**)&pooled_p, g_pooled);
    cudaGetSymbolAddress((void**)&gcnt_p, g_gcnt);

    // ---- CSR build (edges are identical across layers; build once) ----
    zero_i_kernel<<<(NN + 255) / 256, 256>>>(deg_p, NN);
    hist_kernel<<<(EE + 255) / 256, 256>>>(dstp, deg_p, EE);
    scan_kernel<<<1, 1024>>>(deg_p, rowptr_p, NN);
    cursor_init_kernel<<<(NN + 255) / 256, 256>>>(rowptr_p, cursor_p, NN);
    scatter_kernel<<<(EE + 255) / 256, 256>>>(srcp, dstp, cursor_p, csrsrc_p, EE);

    dim3 ggrid((NN + BM - 1) / BM, HC / BN, 4);
    int attn_blocks = (NN + 7) / 8;

    // ---- layer 0 (input x, K=128) ----
    {
        GemmPtrs P;
        P.W[0] = Wq0; P.W[1] = Wk0; P.W[2] = Wv0; P.W[3] = Ws0;
        P.b[0] = bq0; P.b[1] = bk0; P.b[2] = bv0; P.b[3] = bs0;
        P.C[0] = q_p; P.C[1] = k_p; P.C[2] = v_p; P.C[3] = skip_p;
        gemm4_kernel<<<ggrid, 256>>>(x, IN_F, P, NN);
        attn_kernel<<<attn_blocks, 256>>>(q_p, k_p, v_p, skip_p, rowptr_p, csrsrc_p, h_p, NN);
    }

    // ---- layers 1..3 (input g_h, K=256) ----
    for (int l = 0; l < NLAYERS - 1; l++) {
        GemmPtrs P;
        size_t wo = (size_t)l * HC * HC;
        size_t bo = (size_t)l * HC;
        P.W[0] = Wq + wo; P.W[1] = Wk + wo; P.W[2] = Wv + wo; P.W[3] = Ws + wo;
        P.b[0] = bq + bo; P.b[1] = bk + bo; P.b[2] = bv + bo; P.b[3] = bs + bo;
        P.C[0] = q_p; P.C[1] = k_p; P.C[2] = v_p; P.C[3] = skip_p;
        gemm4_kernel<<<ggrid, 256>>>(h_p, HC, P, NN);
        attn_kernel<<<attn_blocks, 256>>>(q_p, k_p, v_p, skip_p, rowptr_p, csrsrc_p, h_p, NN);
    }

    // ---- global mean pool + FC ----
    zero_f_kernel<<<(GG * HC + 255) / 256, 256>>>(pooled_p, GG * HC);
    zero_i_kernel<<<1, 64>>>(gcnt_p, GG);
    pool_cnt_kernel<<<(NN + 255) / 256, 256>>>(batch, gcnt_p, NN);
    pool_sum_kernel<<<(NN * 64 + 255) / 256, 256>>>(h_p, batch, pooled_p, NN);
    fc_kernel<<<GG, OUTF>>>(pooled_p, gcnt_p, Wfc, bfc, out);
}

// round 2
// speedup vs baseline: 1.3985x; 1.3985x over previous
#include <cuda_runtime.h>
#include <cstdint>

#define NN 50000
#define EE 800000
#define IN_F 128
#define HC 256
#define NHEAD 8
#define CDIM 32
#define GG 64
#define OUTF 64
#define NLAYERS 4

// ---------------- scratch (device globals; no allocation allowed) ----------------
__device__ float g_q[(size_t)NN * HC];
__device__ float g_k[(size_t)NN * HC];
__device__ float g_v[(size_t)NN * HC];
__device__ float g_skip[(size_t)NN * HC];
__device__ float g_h[(size_t)NN * HC];
__device__ int   g_deg[NN];
__device__ int   g_rowptr[NN + 1];
__device__ int   g_cursor[NN];
__device__ int   g_csrsrc[EE];
__device__ float g_pooled[GG * HC];
__device__ int   g_gcnt[GG];

// ---------------- small utility kernels ----------------
__global__ void zero_i_kernel(int* p, int n) {
    int i = blockIdx.x * blockDim.x + threadIdx.x;
    if (i < n) p[i] = 0;
}
__global__ void zero_f_kernel(float* p, int n) {
    int i = blockIdx.x * blockDim.x + threadIdx.x;
    if (i < n) p[i] = 0.0f;
}

// ---------------- CSR build ----------------
__global__ void hist_kernel(const int* __restrict__ dst, int* __restrict__ deg, int e) {
    int i = blockIdx.x * blockDim.x + threadIdx.x;
    if (i < e) atomicAdd(&deg[dst[i]], 1);
}

__global__ void scan_kernel(const int* __restrict__ deg, int* __restrict__ rowptr, int n) {
    __shared__ int sh[1024];
    __shared__ int carry;
    int tid = threadIdx.x;
    if (tid == 0) { carry = 0; rowptr[0] = 0; }
    __syncthreads();
    for (int base = 0; base < n; base += 1024) {
        int i = base + tid;
        sh[tid] = (i < n) ? deg[i] : 0;
        __syncthreads();
        for (int off = 1; off < 1024; off <<= 1) {
            int t = (tid >= off) ? sh[tid - off] : 0;
            __syncthreads();
            sh[tid] += t;
            __syncthreads();
        }
        int c = carry;
        if (i < n) rowptr[i + 1] = sh[tid] + c;
        __syncthreads();
        if (tid == 0) carry = c + sh[1023];
        __syncthreads();
    }
}

__global__ void cursor_init_kernel(const int* __restrict__ rowptr, int* __restrict__ cur, int n) {
    int i = blockIdx.x * blockDim.x + threadIdx.x;
    if (i < n) cur[i] = rowptr[i];
}

__global__ void scatter_kernel(const int* __restrict__ src, const int* __restrict__ dst,
                               int* __restrict__ cur, int* __restrict__ csrsrc, int e) {
    int i = blockIdx.x * blockDim.x + threadIdx.x;
    if (i < e) {
        int d = dst[i];
        int pos = atomicAdd(&cur[d], 1);
        csrsrc[pos] = src[i];
    }
}

// ---------------- tf32 tensor-core GEMM ----------------
// C[M,256] = A[M,K] @ W[K,256] + b, 4 weight matrices per launch (blockIdx.z)
struct GemmPtrs {
    const float* W[4];
    const float* b[4];
    float* C[4];
};

#define BM 128
#define BN 64
#define BK 32
#define APITCH 136   // (tig*APITCH + gid) mod 32 covers all banks (136%32==8)
#define BPITCH 72    // 72%32==8 likewise

__device__ __forceinline__ float to_tf32(float x) {
    uint32_t u;
    asm("cvt.rna.tf32.f32 %0, %1;" : "=r"(u) : "f"(x));
    return __uint_as_float(u);
}

__device__ __forceinline__ void mma_tf32(float* d, const uint32_t* a, const uint32_t* b) {
    asm volatile(
        "mma.sync.aligned.m16n8k8.row.col.f32.tf32.tf32.f32 "
        "{%0,%1,%2,%3}, {%4,%5,%6,%7}, {%8,%9}, {%0,%1,%2,%3};"
        : "+f"(d[0]), "+f"(d[1]), "+f"(d[2]), "+f"(d[3])
        : "r"(a[0]), "r"(a[1]), "r"(a[2]), "r"(a[3]), "r"(b[0]), "r"(b[1]));
}

__global__ __launch_bounds__(256) void gemm4_tf32_kernel(const float* __restrict__ A, int K,
                                                         GemmPtrs P, int M) {
    const float* __restrict__ W = P.W[blockIdx.z];
    const float* __restrict__ bias = P.b[blockIdx.z];
    float* __restrict__ C = P.C[blockIdx.z];

    __shared__ float As[BK * APITCH];  // [k][m]
    __shared__ float Bs[BK * BPITCH];  // [k][n]

    int t = threadIdx.x;
    int wid = t >> 5, lane = t & 31;
    int gid = lane >> 2, tig = lane & 3;
    int warpM = wid & 3;        // 0..3 -> 32-row slab
    int warpN = wid >> 2;       // 0..1 -> 32-col slab
    int m0 = blockIdx.x * BM;
    int n0 = blockIdx.y * BN;

    float acc[2][4][4];
#pragma unroll
    for (int mt = 0; mt < 2; mt++)
#pragma unroll
        for (int nt = 0; nt < 4; nt++)
#pragma unroll
            for (int j = 0; j < 4; j++) acc[mt][nt][j] = 0.0f;

    for (int k0 = 0; k0 < K; k0 += BK) {
        // A tile: BM x BK floats = 1024 float4, 4 per thread, cvt to tf32
#pragma unroll
        for (int u = 0; u < 4; u++) {
            int f = t + u * 256;
            int r = f >> 3;        // 0..127
            int c4 = f & 7;        // 0..7 float4 col group
            int gm = m0 + r;
            float4 av = make_float4(0.f, 0.f, 0.f, 0.f);
            if (gm < M) av = *(const float4*)(A + (size_t)gm * K + k0 + c4 * 4);
            As[(c4 * 4 + 0) * APITCH + r] = to_tf32(av.x);
            As[(c4 * 4 + 1) * APITCH + r] = to_tf32(av.y);
            As[(c4 * 4 + 2) * APITCH + r] = to_tf32(av.z);
            As[(c4 * 4 + 3) * APITCH + r] = to_tf32(av.w);
        }
        // B tile: BK x BN floats = 512 float4, 2 per thread
#pragma unroll
        for (int u = 0; u < 2; u++) {
            int f = t + u * 256;
            int kr = f >> 4;       // 0..31
            int c4 = f & 15;       // 0..15
            float4 bv = *(const float4*)(W + (size_t)(k0 + kr) * HC + n0 + c4 * 4);
            Bs[kr * BPITCH + c4 * 4 + 0] = to_tf32(bv.x);
            Bs[kr * BPITCH + c4 * 4 + 1] = to_tf32(bv.y);
            Bs[kr * BPITCH + c4 * 4 + 2] = to_tf32(bv.z);
            Bs[kr * BPITCH + c4 * 4 + 3] = to_tf32(bv.w);
        }
        __syncthreads();

#pragma unroll
        for (int ks = 0; ks < 4; ks++) {
            int kb = ks * 8;
            uint32_t a[2][4];
#pragma unroll
            for (int mt = 0; mt < 2; mt++) {
                int m = warpM * 32 + mt * 16 + gid;
                // mma A frag: a0=(g,tig) a1=(g+8,tig) a2=(g,tig+4) a3=(g+8,tig+4)
                a[mt][0] = __float_as_uint(As[(kb + tig) * APITCH + m]);
                a[mt][1] = __float_as_uint(As[(kb + tig) * APITCH + m + 8]);
                a[mt][2] = __float_as_uint(As[(kb + tig + 4) * APITCH + m]);
                a[mt][3] = __float_as_uint(As[(kb + tig + 4) * APITCH + m + 8]);
            }
            uint32_t b[4][2];
#pragma unroll
            for (int nt = 0; nt < 4; nt++) {
                int n = warpN * 32 + nt * 8 + gid;
                // mma B frag: b0=(k=tig, n=g) b1=(k=tig+4, n=g)
                b[nt][0] = __float_as_uint(Bs[(kb + tig) * BPITCH + n]);
                b[nt][1] = __float_as_uint(Bs[(kb + tig + 4) * BPITCH + n]);
            }
#pragma unroll
            for (int mt = 0; mt < 2; mt++)
#pragma unroll
                for (int nt = 0; nt < 4; nt++) mma_tf32(acc[mt][nt], a[mt], b[nt]);
        }
        __syncthreads();
    }

    // epilogue: C frag c0=(g,2tig) c1=(g,2tig+1) c2=(g+8,2tig) c3=(g+8,2tig+1)
#pragma unroll
    for (int mt = 0; mt < 2; mt++) {
#pragma unroll
        for (int nt = 0; nt < 4; nt++) {
            int n = n0 + warpN * 32 + nt * 8 + tig * 2;
            float b0 = bias[n];
            float b1 = bias[n + 1];
            int row0 = m0 + warpM * 32 + mt * 16 + gid;
            int row1 = row0 + 8;
            if (row0 < M) {
                float2 o = make_float2(acc[mt][nt][0] + b0, acc[mt][nt][1] + b1);
                *(float2*)(C + (size_t)row0 * HC + n) = o;
            }
            if (row1 < M) {
                float2 o = make_float2(acc[mt][nt][2] + b0, acc[mt][nt][3] + b1);
                *(float2*)(C + (size_t)row1 * HC + n) = o;
            }
        }
    }
}

// ---------------- attention: one warp per dst node, streaming softmax ----------------
__global__ __launch_bounds__(256) void attn_kernel(
    const float* __restrict__ q, const float* __restrict__ k,
    const float* __restrict__ v, const float* __restrict__ skp,
    const int* __restrict__ rowptr, const int* __restrict__ srcs,
    float* __restrict__ hout, int n_nodes) {

    int warp = (blockIdx.x * blockDim.x + threadIdx.x) >> 5;
    int lane = threadIdx.x & 31;
    if (warp >= n_nodes) return;

    // lane l owns channels [8l, 8l+8) -> head l/4
    const float4* qp = (const float4*)(q + (size_t)warp * HC);
    float4 q1 = qp[lane * 2];
    float4 q2 = qp[lane * 2 + 1];

    float m = -1e30f;
    float ssum = 0.0f;
    float acc0 = 0.f, acc1 = 0.f, acc2 = 0.f, acc3 = 0.f;
    float acc4 = 0.f, acc5 = 0.f, acc6 = 0.f, acc7 = 0.f;

    const float scale = 0.17677669529663687f;  // 1/sqrt(32)

    int e0 = rowptr[warp];
    int e1 = rowptr[warp + 1];
    for (int e = e0; e < e1; e++) {
        int s = srcs[e];
        const float4* kp = (const float4*)(k + (size_t)s * HC);
        float4 k1 = kp[lane * 2];
        float4 k2 = kp[lane * 2 + 1];
        float d = q1.x * k1.x + q1.y * k1.y + q1.z * k1.z + q1.w * k1.w +
                  q2.x * k2.x + q2.y * k2.y + q2.z * k2.z + q2.w * k2.w;
        d += __shfl_xor_sync(0xffffffffu, d, 1);
        d += __shfl_xor_sync(0xffffffffu, d, 2);
        float logit = d * scale;
        float mn = fmaxf(m, logit);
        float corr = __expf(m - mn);
        float p = __expf(logit - mn);
        m = mn;
        ssum = ssum * corr + p;
        const float4* vp = (const float4*)(v + (size_t)s * HC);
        float4 v1 = vp[lane * 2];
        float4 v2 = vp[lane * 2 + 1];
        acc0 = acc0 * corr + p * v1.x;
        acc1 = acc1 * corr + p * v1.y;
        acc2 = acc2 * corr + p * v1.z;
        acc3 = acc3 * corr + p * v1.w;
        acc4 = acc4 * corr + p * v2.x;
        acc5 = acc5 * corr + p * v2.y;
        acc6 = acc6 * corr + p * v2.z;
        acc7 = acc7 * corr + p * v2.w;
    }
    float inv = 1.0f / (ssum + 1e-16f);
    const float4* sp = (const float4*)(skp + (size_t)warp * HC);
    float4 s1 = sp[lane * 2];
    float4 s2 = sp[lane * 2 + 1];
    float4 o1, o2;
    o1.x = fmaxf(acc0 * inv + s1.x, 0.f);
    o1.y = fmaxf(acc1 * inv + s1.y, 0.f);
    o1.z = fmaxf(acc2 * inv + s1.z, 0.f);
    o1.w = fmaxf(acc3 * inv + s1.w, 0.f);
    o2.x = fmaxf(acc4 * inv + s2.x, 0.f);
    o2.y = fmaxf(acc5 * inv + s2.y, 0.f);
    o2.z = fmaxf(acc6 * inv + s2.z, 0.f);
    o2.w = fmaxf(acc7 * inv + s2.w, 0.f);
    float4* op = (float4*)(hout + (size_t)warp * HC);
    op[lane * 2] = o1;
    op[lane * 2 + 1] = o2;
}

// ---------------- pooling + FC ----------------
__global__ void pool_cnt_kernel(const int* __restrict__ batch, int* __restrict__ cnt, int n) {
    int i = blockIdx.x * blockDim.x + threadIdx.x;
    if (i < n) atomicAdd(&cnt[batch[i]], 1);
}

__global__ void pool_sum_kernel(const float* __restrict__ h, const int* __restrict__ batch,
                                float* __restrict__ pooled, int n) {
    int tid = blockIdx.x * blockDim.x + threadIdx.x;
    if (tid >= n * 64) return;
    int node = tid >> 6;
    int c4 = tid & 63;
    int g = batch[node];
    float4 hv = *(const float4*)(h + (size_t)node * HC + c4 * 4);
    atomicAdd(&pooled[g * HC + c4 * 4 + 0], hv.x);
    atomicAdd(&pooled[g * HC + c4 * 4 + 1], hv.y);
    atomicAdd(&pooled[g * HC + c4 * 4 + 2], hv.z);
    atomicAdd(&pooled[g * HC + c4 * 4 + 3], hv.w);
}

__global__ void fc_kernel(const float* __restrict__ pooled, const int* __restrict__ cnt,
                          const float* __restrict__ Wfc, const float* __restrict__ bfc,
                          float* __restrict__ out) {
    int g = blockIdx.x;
    int o = threadIdx.x;  // 64
    __shared__ float pr[HC];
    float invc = 1.0f / fmaxf((float)cnt[g], 1.0f);
    for (int c = o; c < HC; c += 64) pr[c] = pooled[g * HC + c] * invc;
    __syncthreads();
    float accu = bfc[o];
#pragma unroll 8
    for (int c = 0; c < HC; c++) accu += pr[c] * Wfc[c * OUTF + o];
    out[g * OUTF + o] = accu;
}

// ---------------- host orchestration ----------------
extern "C" void kernel_launch(void* const* d_in, const int* in_sizes, int n_in,
                              void* d_out, int out_size) {
    const float* x = (const float*)d_in[0];
    const int* edge = (const int*)d_in[1];   // [2,E]: row0=src, row1=dst
    const int* batch = (const int*)d_in[2];
    const float* Wq0 = (const float*)d_in[3];
    const float* bq0 = (const float*)d_in[4];
    const float* Wk0 = (const float*)d_in[5];
    const float* bk0 = (const float*)d_in[6];
    const float* Wv0 = (const float*)d_in[7];
    const float* bv0 = (const float*)d_in[8];
    const float* Ws0 = (const float*)d_in[9];
    const float* bs0 = (const float*)d_in[10];
    const float* Wq = (const float*)d_in[11];  // [3,256,256]
    const float* bq = (const float*)d_in[12];
    const float* Wk = (const float*)d_in[13];
    const float* bk = (const float*)d_in[14];
    const float* Wv = (const float*)d_in[15];
    const float* bv = (const float*)d_in[16];
    const float* Ws = (const float*)d_in[17];
    const float* bs = (const float*)d_in[18];
    const float* Wfc = (const float*)d_in[19];
    const float* bfc = (const float*)d_in[20];
    float* out = (float*)d_out;

    const int* srcp = edge;
    const int* dstp = edge + EE;

    float *q_p, *k_p, *v_p, *skip_p, *h_p, *pooled_p;
    int *deg_p, *rowptr_p, *cursor_p, *csrsrc_p, *gcnt_p;
    cudaGetSymbolAddress((void**)&q_p, g_q);
    cudaGetSymbolAddress((void**)&k_p, g_k);
    cudaGetSymbolAddress((void**)&v_p, g_v);
    cudaGetSymbolAddress((void**)&skip_p, g_skip);
    cudaGetSymbolAddress((void**)&h_p, g_h);
    cudaGetSymbolAddress((void**)&deg_p, g_deg);
    cudaGetSymbolAddress((void**)&rowptr_p, g_rowptr);
    cudaGetSymbolAddress((void**)&cursor_p, g_cursor);
    cudaGetSymbolAddress((void**)&csrsrc_p, g_csrsrc);
    cudaGetSymbolAddress((void**)&pooled_p, g_pooled);
    cudaGetSymbolAddress((void**)&gcnt_p, g_gcnt);

    // ---- CSR build (edges identical across layers; build once) ----
    zero_i_kernel<<<(NN + 255) / 256, 256>>>(deg_p, NN);
    hist_kernel<<<(EE + 255) / 256, 256>>>(dstp, deg_p, EE);
    scan_kernel<<<1, 1024>>>(deg_p, rowptr_p, NN);
    cursor_init_kernel<<<(NN + 255) / 256, 256>>>(rowptr_p, cursor_p, NN);
    scatter_kernel<<<(EE + 255) / 256, 256>>>(srcp, dstp, cursor_p, csrsrc_p, EE);

    dim3 ggrid((NN + BM - 1) / BM, HC / BN, 4);
    int attn_blocks = (NN + 7) / 8;

    // ---- layer 0 (input x, K=128) ----
    {
        GemmPtrs P;
        P.W[0] = Wq0; P.W[1] = Wk0; P.W[2] = Wv0; P.W[3] = Ws0;
        P.b[0] = bq0; P.b[1] = bk0; P.b[2] = bv0; P.b[3] = bs0;
        P.C[0] = q_p; P.C[1] = k_p; P.C[2] = v_p; P.C[3] = skip_p;
        gemm4_tf32_kernel<<<ggrid, 256>>>(x, IN_F, P, NN);
        attn_kernel<<<attn_blocks, 256>>>(q_p, k_p, v_p, skip_p, rowptr_p, csrsrc_p, h_p, NN);
    }

    // ---- layers 1..3 (input g_h, K=256) ----
    for (int l = 0; l < NLAYERS - 1; l++) {
        GemmPtrs P;
        size_t wo = (size_t)l * HC * HC;
        size_t bo = (size_t)l * HC;
        P.W[0] = Wq + wo; P.W[1] = Wk + wo; P.W[2] = Wv + wo; P.W[3] = Ws + wo;
        P.b[0] = bq + bo; P.b[1] = bk + bo; P.b[2] = bv + bo; P.b[3] = bs + bo;
        P.C[0] = q_p; P.C[1] = k_p; P.C[2] = v_p; P.C[3] = skip_p;
        gemm4_tf32_kernel<<<ggrid, 256>>>(h_p, HC, P, NN);
        attn_kernel<<<attn_blocks, 256>>>(q_p, k_p, v_p, skip_p, rowptr_p, csrsrc_p, h_p, NN);
    }

    // ---- global mean pool + FC ----
    zero_f_kernel<<<(GG * HC + 255) / 256, 256>>>(pooled_p, GG * HC);
    zero_i_kernel<<<1, 64>>>(gcnt_p, GG);
    pool_cnt_kernel<<<(NN + 255) / 256, 256>>>(batch, gcnt_p, NN);
    pool_sum_kernel<<<(NN * 64 + 255) / 256, 256>>>(h_p, batch, pooled_p, NN);
    fc_kernel<<<GG, OUTF>>>(pooled_p, gcnt_p, Wfc, bfc, out);
}

// round 4
// speedup vs baseline: 1.6471x; 1.1778x over previous
#include <cuda_runtime.h>
#include <cstdint>

#define NN 50000
#define EE 800000
#define IN_F 128
#define HC 256
#define NHEAD 8
#define CDIM 32
#define GG 64
#define OUTF 64
#define NLAYERS 4

// ---------------- scratch (device globals; no allocation allowed) ----------------
__device__ float g_q[(size_t)NN * HC];
__device__ float g_k[(size_t)NN * HC];
__device__ float g_v[(size_t)NN * HC];
__device__ float g_skip[(size_t)NN * HC];
__device__ float g_h[(size_t)NN * HC];
__device__ int   g_deg[NN];
__device__ int   g_rowptr[NN + 1];
__device__ int   g_cursor[NN];
__device__ int   g_csrsrc[EE];
__device__ float g_pooled[GG * HC];
__device__ int   g_gcnt[GG];

// ---------------- small utility kernels ----------------
__global__ void zero_i_kernel(int* p, int n) {
    int i = blockIdx.x * blockDim.x + threadIdx.x;
    if (i < n) p[i] = 0;
}
__global__ void zero_f_kernel(float* p, int n) {
    int i = blockIdx.x * blockDim.x + threadIdx.x;
    if (i < n) p[i] = 0.0f;
}

// ---------------- CSR build ----------------
__global__ void hist_kernel(const int* __restrict__ dst, int* __restrict__ deg, int e) {
    int i = blockIdx.x * blockDim.x + threadIdx.x;
    if (i < e) atomicAdd(&deg[dst[i]], 1);
}

__global__ void scan_kernel(const int* __restrict__ deg, int* __restrict__ rowptr, int n) {
    __shared__ int sh[1024];
    __shared__ int carry;
    int tid = threadIdx.x;
    if (tid == 0) { carry = 0; rowptr[0] = 0; }
    __syncthreads();
    for (int base = 0; base < n; base += 1024) {
        int i = base + tid;
        sh[tid] = (i < n) ? deg[i] : 0;
        __syncthreads();
        for (int off = 1; off < 1024; off <<= 1) {
            int t = (tid >= off) ? sh[tid - off] : 0;
            __syncthreads();
            sh[tid] += t;
            __syncthreads();
        }
        int c = carry;
        if (i < n) rowptr[i + 1] = sh[tid] + c;
        __syncthreads();
        if (tid == 0) carry = c + sh[1023];
        __syncthreads();
    }
}

__global__ void cursor_init_kernel(const int* __restrict__ rowptr, int* __restrict__ cur, int n) {
    int i = blockIdx.x * blockDim.x + threadIdx.x;
    if (i < n) cur[i] = rowptr[i];
}

__global__ void scatter_kernel(const int* __restrict__ src, const int* __restrict__ dst,
                               int* __restrict__ cur, int* __restrict__ csrsrc, int e) {
    int i = blockIdx.x * blockDim.x + threadIdx.x;
    if (i < e) {
        int d = dst[i];
        int pos = atomicAdd(&cur[d], 1);
        csrsrc[pos] = src[i];
    }
}

// ---------------- tf32 tensor-core GEMM, reg-double-buffered ----------------
// C[M,256] = A[M,K] @ W[K,256] + b, 4 weight matrices per launch (blockIdx.z),
// N split in halves (blockIdx.y): BM=128, BN=128, BK=32.
struct GemmPtrs {
    const float* W[4];
    const float* b[4];
    float* C[4];
};

#define BM 128
#define BN 128
#define BK 32
#define APITCH 136
#define BPITCH 136

__device__ __forceinline__ float to_tf32(float x) {
    uint32_t u;
    asm("cvt.rna.tf32.f32 %0, %1;" : "=r"(u) : "f"(x));
    return __uint_as_float(u);
}

__device__ __forceinline__ void mma_tf32(float* d, const uint32_t* a, const uint32_t* b) {
    asm volatile(
        "mma.sync.aligned.m16n8k8.row.col.f32.tf32.tf32.f32 "
        "{%0,%1,%2,%3}, {%4,%5,%6,%7}, {%8,%9}, {%0,%1,%2,%3};"
        : "+f"(d[0]), "+f"(d[1]), "+f"(d[2]), "+f"(d[3])
        : "r"(a[0]), "r"(a[1]), "r"(a[2]), "r"(a[3]), "r"(b[0]), "r"(b[1]));
}

__global__ __launch_bounds__(256) void gemm4_tf32_kernel(const float* __restrict__ A, int K,
                                                         GemmPtrs P, int M) {
    const float* __restrict__ W = P.W[blockIdx.z];
    const float* __restrict__ bias = P.b[blockIdx.z];
    float* __restrict__ C = P.C[blockIdx.z];

    __shared__ float As[BK * APITCH];  // [k][m] transposed
    __shared__ float Bs[BK * BPITCH];  // [k][n]

    int t = threadIdx.x;
    int wid = t >> 5, lane = t & 31;
    int gid = lane >> 2, tig = lane & 3;
    int warpM = wid & 3;        // 0..3 -> 32-row slab
    int warpN = wid >> 2;       // 0..1 -> 64-col slab
    int m0 = blockIdx.x * BM;
    int n0 = blockIdx.y * BN;

    float acc[2][8][4];
#pragma unroll
    for (int mt = 0; mt < 2; mt++)
#pragma unroll
        for (int nt = 0; nt < 8; nt++)
#pragma unroll
            for (int j = 0; j < 4; j++) acc[mt][nt][j] = 0.0f;

    float4 pa[4], pb[4];
    int ntiles = K / BK;

    // prefetch tile 0
#pragma unroll
    for (int u = 0; u < 4; u++) {
        int f = t + u * 256;
        int r = f >> 3, c4 = f & 7;
        int gm = m0 + r;
        pa[u] = (gm < M) ? *(const float4*)(A + (size_t)gm * K + c4 * 4)
                         : make_float4(0.f, 0.f, 0.f, 0.f);
        int kr = f >> 5, bc4 = f & 31;
        pb[u] = *(const float4*)(W + (size_t)kr * HC + n0 + bc4 * 4);
    }

    for (int tile = 0; tile < ntiles; tile++) {
        // store prefetched tile to smem (cvt to tf32)
#pragma unroll
        for (int u = 0; u < 4; u++) {
            int f = t + u * 256;
            int r = f >> 3, c4 = f & 7;
            As[(c4 * 4 + 0) * APITCH + r] = to_tf32(pa[u].x);
            As[(c4 * 4 + 1) * APITCH + r] = to_tf32(pa[u].y);
            As[(c4 * 4 + 2) * APITCH + r] = to_tf32(pa[u].z);
            As[(c4 * 4 + 3) * APITCH + r] = to_tf32(pa[u].w);
            int kr = f >> 5, bc4 = f & 31;
            Bs[kr * BPITCH + bc4 * 4 + 0] = to_tf32(pb[u].x);
            Bs[kr * BPITCH + bc4 * 4 + 1] = to_tf32(pb[u].y);
            Bs[kr * BPITCH + bc4 * 4 + 2] = to_tf32(pb[u].z);
            Bs[kr * BPITCH + bc4 * 4 + 3] = to_tf32(pb[u].w);
        }
        __syncthreads();

        // issue global loads for next tile (overlap with mma below)
        if (tile + 1 < ntiles) {
            int k0 = (tile + 1) * BK;
#pragma unroll
            for (int u = 0; u < 4; u++) {
                int f = t + u * 256;
                int r = f >> 3, c4 = f & 7;
                int gm = m0 + r;
                pa[u] = (gm < M) ? *(const float4*)(A + (size_t)gm * K + k0 + c4 * 4)
                                 : make_float4(0.f, 0.f, 0.f, 0.f);
                int kr = f >> 5, bc4 = f & 31;
                pb[u] = *(const float4*)(W + (size_t)(k0 + kr) * HC + n0 + bc4 * 4);
            }
        }

#pragma unroll
        for (int ks = 0; ks < 4; ks++) {
            int kb = ks * 8;
            uint32_t a[2][4];
#pragma unroll
            for (int mt = 0; mt < 2; mt++) {
                int m = warpM * 32 + mt * 16 + gid;
                a[mt][0] = __float_as_uint(As[(kb + tig) * APITCH + m]);
                a[mt][1] = __float_as_uint(As[(kb + tig) * APITCH + m + 8]);
                a[mt][2] = __float_as_uint(As[(kb + tig + 4) * APITCH + m]);
                a[mt][3] = __float_as_uint(As[(kb + tig + 4) * APITCH + m + 8]);
            }
            uint32_t b[8][2];
#pragma unroll
            for (int nt = 0; nt < 8; nt++) {
                int n = warpN * 64 + nt * 8 + gid;
                b[nt][0] = __float_as_uint(Bs[(kb + tig) * BPITCH + n]);
                b[nt][1] = __float_as_uint(Bs[(kb + tig + 4) * BPITCH + n]);
            }
#pragma unroll
            for (int mt = 0; mt < 2; mt++)
#pragma unroll
                for (int nt = 0; nt < 8; nt++) mma_tf32(acc[mt][nt], a[mt], b[nt]);
        }
        __syncthreads();
    }

    // epilogue
#pragma unroll
    for (int mt = 0; mt < 2; mt++) {
#pragma unroll
        for (int nt = 0; nt < 8; nt++) {
            int n = n0 + warpN * 64 + nt * 8 + tig * 2;
            float b0 = bias[n];
            float b1 = bias[n + 1];
            int row0 = m0 + warpM * 32 + mt * 16 + gid;
            int row1 = row0 + 8;
            if (row0 < M) {
                float2 o = make_float2(acc[mt][nt][0] + b0, acc[mt][nt][1] + b1);
                *(float2*)(C + (size_t)row0 * HC + n) = o;
            }
            if (row1 < M) {
                float2 o = make_float2(acc[mt][nt][2] + b0, acc[mt][nt][3] + b1);
                *(float2*)(C + (size_t)row1 * HC + n) = o;
            }
        }
    }
}

// ---------------- attention: one warp per dst node, streaming softmax, sw pipelined ----------------
__global__ __launch_bounds__(256) void attn_kernel(
    const float* __restrict__ q, const float* __restrict__ k,
    const float* __restrict__ v, const float* __restrict__ skp,
    const int* __restrict__ rowptr, const int* __restrict__ srcs,
    float* __restrict__ hout, int n_nodes) {

    int warp = (blockIdx.x * blockDim.x + threadIdx.x) >> 5;
    int lane = threadIdx.x & 31;
    if (warp >= n_nodes) return;

    const float4* qp = (const float4*)(q + (size_t)warp * HC);
    float4 q1 = qp[lane * 2];
    float4 q2 = qp[lane * 2 + 1];

    float m = -1e30f;
    float ssum = 0.0f;
    float acc0 = 0.f, acc1 = 0.f, acc2 = 0.f, acc3 = 0.f;
    float acc4 = 0.f, acc5 = 0.f, acc6 = 0.f, acc7 = 0.f;

    const float scale = 0.17677669529663687f;  // 1/sqrt(32)

    int e0 = rowptr[warp];
    int e1 = rowptr[warp + 1];

    float4 k1, k2, v1, v2;
    if (e0 < e1) {
        int s = srcs[e0];
        const float4* kp = (const float4*)(k + (size_t)s * HC);
        k1 = kp[lane * 2]; k2 = kp[lane * 2 + 1];
        const float4* vp = (const float4*)(v + (size_t)s * HC);
        v1 = vp[lane * 2]; v2 = vp[lane * 2 + 1];
    }
    for (int e = e0; e < e1; e++) {
        float4 ck1 = k1, ck2 = k2, cv1 = v1, cv2 = v2;
        if (e + 1 < e1) {
            int s2 = srcs[e + 1];
            const float4* kp = (const float4*)(k + (size_t)s2 * HC);
            k1 = kp[lane * 2]; k2 = kp[lane * 2 + 1];
            const float4* vp = (const float4*)(v + (size_t)s2 * HC);
            v1 = vp[lane * 2]; v2 = vp[lane * 2 + 1];
        }
        float d = q1.x * ck1.x + q1.y * ck1.y + q1.z * ck1.z + q1.w * ck1.w +
                  q2.x * ck2.x + q2.y * ck2.y + q2.z * ck2.z + q2.w * ck2.w;
        d += __shfl_xor_sync(0xffffffffu, d, 1);
        d += __shfl_xor_sync(0xffffffffu, d, 2);
        float logit = d * scale;
        float mn = fmaxf(m, logit);
        float corr = __expf(m - mn);
        float p = __expf(logit - mn);
        m = mn;
        ssum = ssum * corr + p;
        acc0 = acc0 * corr + p * cv1.x;
        acc1 = acc1 * corr + p * cv1.y;
        acc2 = acc2 * corr + p * cv1.z;
        acc3 = acc3 * corr + p * cv1.w;
        acc4 = acc4 * corr + p * cv2.x;
        acc5 = acc5 * corr + p * cv2.y;
        acc6 = acc6 * corr + p * cv2.z;
        acc7 = acc7 * corr + p * cv2.w;
    }
    float inv = 1.0f / (ssum + 1e-16f);
    const float4* sp = (const float4*)(skp + (size_t)warp * HC);
    float4 s1 = sp[lane * 2];
    float4 s2 = sp[lane * 2 + 1];
    float4 o1, o2;
    o1.x = fmaxf(acc0 * inv + s1.x, 0.f);
    o1.y = fmaxf(acc1 * inv + s1.y, 0.f);
    o1.z = fmaxf(acc2 * inv + s1.z, 0.f);
    o1.w = fmaxf(acc3 * inv + s1.w, 0.f);
    o2.x = fmaxf(acc4 * inv + s2.x, 0.f);
    o2.y = fmaxf(acc5 * inv + s2.y, 0.f);
    o2.z = fmaxf(acc6 * inv + s2.z, 0.f);
    o2.w = fmaxf(acc7 * inv + s2.w, 0.f);
    float4* op = (float4*)(hout + (size_t)warp * HC);
    op[lane * 2] = o1;
    op[lane * 2 + 1] = o2;
}

// ---------------- pooling + FC ----------------
__global__ void pool_cnt_kernel(const int* __restrict__ batch, int* __restrict__ cnt, int n) {
    int i = blockIdx.x * blockDim.x + threadIdx.x;
    if (i < n) atomicAdd(&cnt[batch[i]], 1);
}

// batch is sorted: per-thread run-length accumulation, atomic flush only at group change
#define POOL_NODES 128
__global__ __launch_bounds__(256) void pool_sum_kernel(const float* __restrict__ h,
                                                       const int* __restrict__ batch,
                                                       float* __restrict__ pooled, int n) {
    int c = threadIdx.x;                 // channel 0..255
    int node0 = blockIdx.x * POOL_NODES;
    int nodeEnd = min(node0 + POOL_NODES, n);
    int curg = batch[node0];
    float accu = 0.0f;
    for (int node = node0; node < nodeEnd; node++) {
        int g = batch[node];
        if (g != curg) {
            atomicAdd(&pooled[curg * HC + c], accu);
            accu = 0.0f;
            curg = g;
        }
        accu += h[(size_t)node * HC + c];
    }
    atomicAdd(&pooled[curg * HC + c], accu);
}

__global__ void fc_kernel(const float* __restrict__ pooled, const int* __restrict__ cnt,
                          const float* __restrict__ Wfc, const float* __restrict__ bfc,
                          float* __restrict__ out) {
    int g = blockIdx.x;
    int o = threadIdx.x;  // 64
    __shared__ float pr[HC];
    float invc = 1.0f / fmaxf((float)cnt[g], 1.0f);
    for (int c = o; c < HC; c += 64) pr[c] = pooled[g * HC + c] * invc;
    __syncthreads();
    float accu = bfc[o];
#pragma unroll 8
    for (int c = 0; c < HC; c++) accu += pr[c] * Wfc[c * OUTF + o];
    out[g * OUTF + o] = accu;
}

// ---------------- host orchestration ----------------
extern "C" void kernel_launch(void* const* d_in, const int* in_sizes, int n_in,
                              void* d_out, int out_size) {
    const float* x = (const float*)d_in[0];
    const int* edge = (const int*)d_in[1];   // [2,E]: row0=src, row1=dst
    const int* batch = (const int*)d_in[2];
    const float* Wq0 = (const float*)d_in[3];
    const float* bq0 = (const float*)d_in[4];
    const float* Wk0 = (const float*)d_in[5];
    const float* bk0 = (const float*)d_in[6];
    const float* Wv0 = (const float*)d_in[7];
    const float* bv0 = (const float*)d_in[8];
    const float* Ws0 = (const float*)d_in[9];
    const float* bs0 = (const float*)d_in[10];
    const float* Wq = (const float*)d_in[11];  // [3,256,256]
    const float* bq = (const float*)d_in[12];
    const float* Wk = (const float*)d_in[13];
    const float* bk = (const float*)d_in[14];
    const float* Wv = (const float*)d_in[15];
    const float* bv = (const float*)d_in[16];
    const float* Ws = (const float*)d_in[17];
    const float* bs = (const float*)d_in[18];
    const float* Wfc = (const float*)d_in[19];
    const float* bfc = (const float*)d_in[20];
    float* out = (float*)d_out;

    const int* srcp = edge;
    const int* dstp = edge + EE;

    float *q_p, *k_p, *v_p, *skip_p, *h_p, *pooled_p;
    int *deg_p, *rowptr_p, *cursor_p, *csrsrc_p, *gcnt_p;
    cudaGetSymbolAddress((void**)&q_p, g_q);
    cudaGetSymbolAddress((void**)&k_p, g_k);
    cudaGetSymbolAddress((void**)&v_p, g_v);
    cudaGetSymbolAddress((void**)&skip_p, g_skip);
    cudaGetSymbolAddress((void**)&h_p, g_h);
    cudaGetSymbolAddress((void**)&deg_p, g_deg);
    cudaGetSymbolAddress((void**)&rowptr_p, g_rowptr);
    cudaGetSymbolAddress((void**)&cursor_p, g_cursor);
    cudaGetSymbolAddress((void**)&csrsrc_p, g_csrsrc);
    cudaGetSymbolAddress((void**)&pooled_p, g_pooled);
    cudaGetSymbolAddress((void**)&gcnt_p, g_gcnt);

    // ---- CSR build (edges identical across layers; build once) ----
    zero_i_kernel<<<(NN + 255) / 256, 256>>>(deg_p, NN);
    hist_kernel<<<(EE + 255) / 256, 256>>>(dstp, deg_p, EE);
    scan_kernel<<<1, 1024>>>(deg_p, rowptr_p, NN);
    cursor_init_kernel<<<(NN + 255) / 256, 256>>>(rowptr_p, cursor_p, NN);
    scatter_kernel<<<(EE + 255) / 256, 256>>>(srcp, dstp, cursor_p, csrsrc_p, EE);

    dim3 ggrid((NN + BM - 1) / BM, HC / BN, 4);  // y: 2 halves of 256 cols (BN=128)
    int attn_blocks = (NN + 7) / 8;

    // ---- layer 0 (input x, K=128) ----
    {
        GemmPtrs P;
        P.W[0] = Wq0; P.W[1] = Wk0; P.W[2] = Wv0; P.W[3] = Ws0;
        P.b[0] = bq0; P.b[1] = bk0; P.b[2] = bv0; P.b[3] = bs0;
        P.C[0] = q_p; P.C[1] = k_p; P.C[2] = v_p; P.C[3] = skip_p;
        gemm4_tf32_kernel<<<ggrid, 256>>>(x, IN_F, P, NN);
        attn_kernel<<<attn_blocks, 256>>>(q_p, k_p, v_p, skip_p, rowptr_p, csrsrc_p, h_p, NN);
    }

    // ---- layers 1..3 (input g_h, K=256) ----
    for (int l = 0; l < NLAYERS - 1; l++) {
        GemmPtrs P;
        size_t wo = (size_t)l * HC * HC;
        size_t bo = (size_t)l * HC;
        P.W[0] = Wq + wo; P.W[1] = Wk + wo; P.W[2] = Wv + wo; P.W[3] = Ws + wo;
        P.b[0] = bq + bo; P.b[1] = bk + bo; P.b[2] = bv + bo; P.b[3] = bs + bo;
        P.C[0] = q_p; P.C[1] = k_p; P.C[2] = v_p; P.C[3] = skip_p;
        gemm4_tf32_kernel<<<ggrid, 256>>>(h_p, HC, P, NN);
        attn_kernel<<<attn_blocks, 256>>>(q_p, k_p, v_p, skip_p, rowptr_p, csrsrc_p, h_p, NN);
    }

    // ---- global mean pool + FC ----
    zero_f_kernel<<<(GG * HC + 255) / 256, 256>>>(pooled_p, GG * HC);
    zero_i_kernel<<<1, 64>>>(gcnt_p, GG);
    pool_cnt_kernel<<<(NN + 255) / 256, 256>>>(batch, gcnt_p, NN);
    pool_sum_kernel<<<(NN + POOL_NODES - 1) / POOL_NODES, 256>>>(h_p, batch, pooled_p, NN);
    fc_kernel<<<GG, OUTF>>>(pooled_p, gcnt_p, Wfc, bfc, out);
}

// round 6
// speedup vs baseline: 1.8935x; 1.1496x over previous
#include <cuda_runtime.h>
#include <cuda_bf16.h>
#include <cstdint>

#define NN 50000
#define EE 800000
#define IN_F 128
#define HC 256
#define NHEAD 8
#define CDIM 32
#define GG 64
#define OUTF 64
#define NLAYERS 4

// ---------------- scratch (device globals; no allocation allowed) ----------------
__device__ float g_q[(size_t)NN * HC];
__device__ __nv_bfloat16 g_kb[(size_t)NN * HC];
__device__ __nv_bfloat16 g_vb[(size_t)NN * HC];
__device__ float g_skip[(size_t)NN * HC];
__device__ float g_h[(size_t)NN * HC];
__device__ int   g_deg[NN];
__device__ int   g_rowptr[NN + 1];
__device__ int   g_cursor[NN];
__device__ int   g_csrsrc[EE];
__device__ float g_pooled[GG * HC];
__device__ int   g_gcnt[GG];

// ---------------- small utility kernels ----------------
__global__ void zero_i_kernel(int* p, int n) {
    int i = blockIdx.x * blockDim.x + threadIdx.x;
    if (i < n) p[i] = 0;
}
__global__ void zero_f_kernel(float* p, int n) {
    int i = blockIdx.x * blockDim.x + threadIdx.x;
    if (i < n) p[i] = 0.0f;
}

// ---------------- CSR build ----------------
__global__ void hist_kernel(const int* __restrict__ dst, int* __restrict__ deg, int e) {
    int i = blockIdx.x * blockDim.x + threadIdx.x;
    if (i < e) atomicAdd(&deg[dst[i]], 1);
}

__global__ void scan_kernel(const int* __restrict__ deg, int* __restrict__ rowptr, int n) {
    __shared__ int sh[1024];
    __shared__ int carry;
    int tid = threadIdx.x;
    if (tid == 0) { carry = 0; rowptr[0] = 0; }
    __syncthreads();
    for (int base = 0; base < n; base += 1024) {
        int i = base + tid;
        sh[tid] = (i < n) ? deg[i] : 0;
        __syncthreads();
        for (int off = 1; off < 1024; off <<= 1) {
            int t = (tid >= off) ? sh[tid - off] : 0;
            __syncthreads();
            sh[tid] += t;
            __syncthreads();
        }
        int c = carry;
        if (i < n) rowptr[i + 1] = sh[tid] + c;
        __syncthreads();
        if (tid == 0) carry = c + sh[1023];
        __syncthreads();
    }
}

__global__ void cursor_init_kernel(const int* __restrict__ rowptr, int* __restrict__ cur, int n) {
    int i = blockIdx.x * blockDim.x + threadIdx.x;
    if (i < n) cur[i] = rowptr[i];
}

__global__ void scatter_kernel(const int* __restrict__ src, const int* __restrict__ dst,
                               int* __restrict__ cur, int* __restrict__ csrsrc, int e) {
    int i = blockIdx.x * blockDim.x + threadIdx.x;
    if (i < e) {
        int d = dst[i];
        int pos = atomicAdd(&cur[d], 1);
        csrsrc[pos] = src[i];
    }
}

// ---------------- tf32 tensor-core GEMM, reg-double-buffered ----------------
// C[M,256] = A[M,K] @ W[K,256] + b, 4 weight matrices per launch (blockIdx.z).
// bf16_mask bit z => output matrix z stored as bf16 (k, v), else fp32 (q, skip).
struct GemmPtrs {
    const float* W[4];
    const float* b[4];
    void* C[4];
    int bf16_mask;
};

#define BM 128
#define BN 128
#define BK 32
#define APITCH 136
#define BPITCH 136

__device__ __forceinline__ float to_tf32(float x) {
    uint32_t u;
    asm("cvt.rna.tf32.f32 %0, %1;" : "=r"(u) : "f"(x));
    return __uint_as_float(u);
}

__device__ __forceinline__ void mma_tf32(float* d, const uint32_t* a, const uint32_t* b) {
    asm volatile(
        "mma.sync.aligned.m16n8k8.row.col.f32.tf32.tf32.f32 "
        "{%0,%1,%2,%3}, {%4,%5,%6,%7}, {%8,%9}, {%0,%1,%2,%3};"
        : "+f"(d[0]), "+f"(d[1]), "+f"(d[2]), "+f"(d[3])
        : "r"(a[0]), "r"(a[1]), "r"(a[2]), "r"(a[3]), "r"(b[0]), "r"(b[1]));
}

__global__ __launch_bounds__(256) void gemm4_tf32_kernel(const float* __restrict__ A, int K,
                                                         GemmPtrs P, int M) {
    const float* __restrict__ W = P.W[blockIdx.z];
    const float* __restrict__ bias = P.b[blockIdx.z];
    bool out_bf16 = (P.bf16_mask >> blockIdx.z) & 1;
    float* __restrict__ Cf = (float*)P.C[blockIdx.z];
    __nv_bfloat16* __restrict__ Cb = (__nv_bfloat16*)P.C[blockIdx.z];

    __shared__ float As[BK * APITCH];  // [k][m] transposed
    __shared__ float Bs[BK * BPITCH];  // [k][n]

    int t = threadIdx.x;
    int wid = t >> 5, lane = t & 31;
    int gid = lane >> 2, tig = lane & 3;
    int warpM = wid & 3;        // 0..3 -> 32-row slab
    int warpN = wid >> 2;       // 0..1 -> 64-col slab
    int m0 = blockIdx.x * BM;
    int n0 = blockIdx.y * BN;

    float acc[2][8][4];
#pragma unroll
    for (int mt = 0; mt < 2; mt++)
#pragma unroll
        for (int nt = 0; nt < 8; nt++)
#pragma unroll
            for (int j = 0; j < 4; j++) acc[mt][nt][j] = 0.0f;

    float4 pa[4], pb[4];
    int ntiles = K / BK;

    // prefetch tile 0
#pragma unroll
    for (int u = 0; u < 4; u++) {
        int f = t + u * 256;
        int r = f >> 3, c4 = f & 7;
        int gm = m0 + r;
        pa[u] = (gm < M) ? *(const float4*)(A + (size_t)gm * K + c4 * 4)
                         : make_float4(0.f, 0.f, 0.f, 0.f);
        int kr = f >> 5, bc4 = f & 31;
        pb[u] = *(const float4*)(W + (size_t)kr * HC + n0 + bc4 * 4);
    }

    for (int tile = 0; tile < ntiles; tile++) {
#pragma unroll
        for (int u = 0; u < 4; u++) {
            int f = t + u * 256;
            int r = f >> 3, c4 = f & 7;
            As[(c4 * 4 + 0) * APITCH + r] = to_tf32(pa[u].x);
            As[(c4 * 4 + 1) * APITCH + r] = to_tf32(pa[u].y);
            As[(c4 * 4 + 2) * APITCH + r] = to_tf32(pa[u].z);
            As[(c4 * 4 + 3) * APITCH + r] = to_tf32(pa[u].w);
            int kr = f >> 5, bc4 = f & 31;
            Bs[kr * BPITCH + bc4 * 4 + 0] = to_tf32(pb[u].x);
            Bs[kr * BPITCH + bc4 * 4 + 1] = to_tf32(pb[u].y);
            Bs[kr * BPITCH + bc4 * 4 + 2] = to_tf32(pb[u].z);
            Bs[kr * BPITCH + bc4 * 4 + 3] = to_tf32(pb[u].w);
        }
        __syncthreads();

        if (tile + 1 < ntiles) {
            int k0 = (tile + 1) * BK;
#pragma unroll
            for (int u = 0; u < 4; u++) {
                int f = t + u * 256;
                int r = f >> 3, c4 = f & 7;
                int gm = m0 + r;
                pa[u] = (gm < M) ? *(const float4*)(A + (size_t)gm * K + k0 + c4 * 4)
                                 : make_float4(0.f, 0.f, 0.f, 0.f);
                int kr = f >> 5, bc4 = f & 31;
                pb[u] = *(const float4*)(W + (size_t)(k0 + kr) * HC + n0 + bc4 * 4);
            }
        }

#pragma unroll
        for (int ks = 0; ks < 4; ks++) {
            int kb = ks * 8;
            uint32_t a[2][4];
#pragma unroll
            for (int mt = 0; mt < 2; mt++) {
                int m = warpM * 32 + mt * 16 + gid;
                a[mt][0] = __float_as_uint(As[(kb + tig) * APITCH + m]);
                a[mt][1] = __float_as_uint(As[(kb + tig) * APITCH + m + 8]);
                a[mt][2] = __float_as_uint(As[(kb + tig + 4) * APITCH + m]);
                a[mt][3] = __float_as_uint(As[(kb + tig + 4) * APITCH + m + 8]);
            }
            uint32_t b[8][2];
#pragma unroll
            for (int nt = 0; nt < 8; nt++) {
                int n = warpN * 64 + nt * 8 + gid;
                b[nt][0] = __float_as_uint(Bs[(kb + tig) * BPITCH + n]);
                b[nt][1] = __float_as_uint(Bs[(kb + tig + 4) * BPITCH + n]);
            }
#pragma unroll
            for (int mt = 0; mt < 2; mt++)
#pragma unroll
                for (int nt = 0; nt < 8; nt++) mma_tf32(acc[mt][nt], a[mt], b[nt]);
        }
        __syncthreads();
    }

    // epilogue
#pragma unroll
    for (int mt = 0; mt < 2; mt++) {
#pragma unroll
        for (int nt = 0; nt < 8; nt++) {
            int n = n0 + warpN * 64 + nt * 8 + tig * 2;
            float b0 = bias[n];
            float b1 = bias[n + 1];
            int row0 = m0 + warpM * 32 + mt * 16 + gid;
            int row1 = row0 + 8;
            float v00 = acc[mt][nt][0] + b0, v01 = acc[mt][nt][1] + b1;
            float v10 = acc[mt][nt][2] + b0, v11 = acc[mt][nt][3] + b1;
            if (out_bf16) {
                if (row0 < M)
                    *(__nv_bfloat162*)(Cb + (size_t)row0 * HC + n) = __floats2bfloat162_rn(v00, v01);
                if (row1 < M)
                    *(__nv_bfloat162*)(Cb + (size_t)row1 * HC + n) = __floats2bfloat162_rn(v10, v11);
            } else {
                if (row0 < M) *(float2*)(Cf + (size_t)row0 * HC + n) = make_float2(v00, v01);
                if (row1 < M) *(float2*)(Cf + (size_t)row1 * HC + n) = make_float2(v10, v11);
            }
        }
    }
}

// ---------------- attention: one warp per dst node, streaming softmax, bf16 k/v ----------------
__global__ __launch_bounds__(256) void attn_kernel(
    const float* __restrict__ q, const __nv_bfloat16* __restrict__ kb,
    const __nv_bfloat16* __restrict__ vb, const float* __restrict__ skp,
    const int* __restrict__ rowptr, const int* __restrict__ srcs,
    float* __restrict__ hout, int n_nodes) {

    int warp = (blockIdx.x * blockDim.x + threadIdx.x) >> 5;
    int lane = threadIdx.x & 31;
    if (warp >= n_nodes) return;

    // lane l owns channels [8l, 8l+8) -> head l/4
    const float4* qp = (const float4*)(q + (size_t)warp * HC);
    float4 q1 = qp[lane * 2];
    float4 q2 = qp[lane * 2 + 1];

    float m = -1e30f;
    float ssum = 0.0f;
    float acc0 = 0.f, acc1 = 0.f, acc2 = 0.f, acc3 = 0.f;
    float acc4 = 0.f, acc5 = 0.f, acc6 = 0.f, acc7 = 0.f;

    const float scale = 0.17677669529663687f;  // 1/sqrt(32)

    int e0 = rowptr[warp];
    int e1 = rowptr[warp + 1];

    uint4 kraw, vraw;
    if (e0 < e1) {
        int s = srcs[e0];
        kraw = *(const uint4*)(kb + (size_t)s * HC + lane * 8);
        vraw = *(const uint4*)(vb + (size_t)s * HC + lane * 8);
    }
    for (int e = e0; e < e1; e++) {
        uint4 ck = kraw, cv = vraw;
        if (e + 1 < e1) {
            int s2 = srcs[e + 1];
            kraw = *(const uint4*)(kb + (size_t)s2 * HC + lane * 8);
            vraw = *(const uint4*)(vb + (size_t)s2 * HC + lane * 8);
        }
        float2 k0 = __bfloat1622float2(*(__nv_bfloat162*)&ck.x);
        float2 k1 = __bfloat1622float2(*(__nv_bfloat162*)&ck.y);
        float2 k2 = __bfloat1622float2(*(__nv_bfloat162*)&ck.z);
        float2 k3 = __bfloat1622float2(*(__nv_bfloat162*)&ck.w);
        float d = q1.x * k0.x + q1.y * k0.y + q1.z * k1.x + q1.w * k1.y +
                  q2.x * k2.x + q2.y * k2.y + q2.z * k3.x + q2.w * k3.y;
        d += __shfl_xor_sync(0xffffffffu, d, 1);
        d += __shfl_xor_sync(0xffffffffu, d, 2);
        float logit = d * scale;
        float mn = fmaxf(m, logit);
        float corr = __expf(m - mn);
        float p = __expf(logit - mn);
        m = mn;
        ssum = ssum * corr + p;
        float2 v0 = __bfloat1622float2(*(__nv_bfloat162*)&cv.x);
        float2 v1 = __bfloat1622float2(*(__nv_bfloat162*)&cv.y);
        float2 v2 = __bfloat1622float2(*(__nv_bfloat162*)&cv.z);
        float2 v3 = __bfloat1622float2(*(__nv_bfloat162*)&cv.w);
        acc0 = acc0 * corr + p * v0.x;
        acc1 = acc1 * corr + p * v0.y;
        acc2 = acc2 * corr + p * v1.x;
        acc3 = acc3 * corr + p * v1.y;
        acc4 = acc4 * corr + p * v2.x;
        acc5 = acc5 * corr + p * v2.y;
        acc6 = acc6 * corr + p * v3.x;
        acc7 = acc7 * corr + p * v3.y;
    }
    float inv = 1.0f / (ssum + 1e-16f);
    const float4* sp = (const float4*)(skp + (size_t)warp * HC);
    float4 s1 = sp[lane * 2];
    float4 s2 = sp[lane * 2 + 1];
    float4 o1, o2;
    o1.x = fmaxf(acc0 * inv + s1.x, 0.f);
    o1.y = fmaxf(acc1 * inv + s1.y, 0.f);
    o1.z = fmaxf(acc2 * inv + s1.z, 0.f);
    o1.w = fmaxf(acc3 * inv + s1.w, 0.f);
    o2.x = fmaxf(acc4 * inv + s2.x, 0.f);
    o2.y = fmaxf(acc5 * inv + s2.y, 0.f);
    o2.z = fmaxf(acc6 * inv + s2.z, 0.f);
    o2.w = fmaxf(acc7 * inv + s2.w, 0.f);
    float4* op = (float4*)(hout + (size_t)warp * HC);
    op[lane * 2] = o1;
    op[lane * 2 + 1] = o2;
}

// ---------------- pooling + FC ----------------
__global__ void pool_cnt_kernel(const int* __restrict__ batch, int* __restrict__ cnt, int n) {
    int i = blockIdx.x * blockDim.x + threadIdx.x;
    if (i < n) atomicAdd(&cnt[batch[i]], 1);
}

#define POOL_NODES 128
__global__ __launch_bounds__(256) void pool_sum_kernel(const float* __restrict__ h,
                                                       const int* __restrict__ batch,
                                                       float* __restrict__ pooled, int n) {
    int c = threadIdx.x;                 // channel 0..255
    int node0 = blockIdx.x * POOL_NODES;
    int nodeEnd = min(node0 + POOL_NODES, n);
    int curg = batch[node0];
    float accu = 0.0f;
    for (int node = node0; node < nodeEnd; node++) {
        int g = batch[node];
        if (g != curg) {
            atomicAdd(&pooled[curg * HC + c], accu);
            accu = 0.0f;
            curg = g;
        }
        accu += h[(size_t)node * HC + c];
    }
    atomicAdd(&pooled[curg * HC + c], accu);
}

__global__ void fc_kernel(const float* __restrict__ pooled, const int* __restrict__ cnt,
                          const float* __restrict__ Wfc, const float* __restrict__ bfc,
                          float* __restrict__ out) {
    int g = blockIdx.x;
    int o = threadIdx.x;  // 64
    __shared__ float pr[HC];
    float invc = 1.0f / fmaxf((float)cnt[g], 1.0f);
    for (int c = o; c < HC; c += 64) pr[c] = pooled[g * HC + c] * invc;
    __syncthreads();
    float accu = bfc[o];
#pragma unroll 8
    for (int c = 0; c < HC; c++) accu += pr[c] * Wfc[c * OUTF + o];
    out[g * OUTF + o] = accu;
}

// ---------------- host orchestration ----------------
extern "C" void kernel_launch(void* const* d_in, const int* in_sizes, int n_in,
                              void* d_out, int out_size) {
    const float* x = (const float*)d_in[0];
    const int* edge = (const int*)d_in[1];   // [2,E]: row0=src, row1=dst
    const int* batch = (const int*)d_in[2];
    const float* Wq0 = (const float*)d_in[3];
    const float* bq0 = (const float*)d_in[4];
    const float* Wk0 = (const float*)d_in[5];
    const float* bk0 = (const float*)d_in[6];
    const float* Wv0 = (const float*)d_in[7];
    const float* bv0 = (const float*)d_in[8];
    const float* Ws0 = (const float*)d_in[9];
    const float* bs0 = (const float*)d_in[10];
    const float* Wq = (const float*)d_in[11];  // [3,256,256]
    const float* bq = (const float*)d_in[12];
    const float* Wk = (const float*)d_in[13];
    const float* bk = (const float*)d_in[14];
    const float* Wv = (const float*)d_in[15];
    const float* bv = (const float*)d_in[16];
    const float* Ws = (const float*)d_in[17];
    const float* bs = (const float*)d_in[18];
    const float* Wfc = (const float*)d_in[19];
    const float* bfc = (const float*)d_in[20];
    float* out = (float*)d_out;

    const int* srcp = edge;
    const int* dstp = edge + EE;

    float *q_p, *skip_p, *h_p, *pooled_p;
    __nv_bfloat16 *kb_p, *vb_p;
    int *deg_p, *rowptr_p, *cursor_p, *csrsrc_p, *gcnt_p;
    cudaGetSymbolAddress((void**)&q_p, g_q);
    cudaGetSymbolAddress((void**)&kb_p, g_kb);
    cudaGetSymbolAddress((void**)&vb_p, g_vb);
    cudaGetSymbolAddress((void**)&skip_p, g_skip);
    cudaGetSymbolAddress((void**)&h_p, g_h);
    cudaGetSymbolAddress((void**)&deg_p, g_deg);
    cudaGetSymbolAddress((void**)&rowptr_p, g_rowptr);
    cudaGetSymbolAddress((void**)&cursor_p, g_cursor);
    cudaGetSymbolAddress((void**)&csrsrc_p, g_csrsrc);
    cudaGetSymbolAddress((void**)&pooled_p, g_pooled);
    cudaGetSymbolAddress((void**)&gcnt_p, g_gcnt);

    // ---- CSR build (edges identical across layers; build once) ----
    zero_i_kernel<<<(NN + 255) / 256, 256>>>(deg_p, NN);
    hist_kernel<<<(EE + 255) / 256, 256>>>(dstp, deg_p, EE);
    scan_kernel<<<1, 1024>>>(deg_p, rowptr_p, NN);
    cursor_init_kernel<<<(NN + 255) / 256, 256>>>(rowptr_p, cursor_p, NN);
    scatter_kernel<<<(EE + 255) / 256, 256>>>(srcp, dstp, cursor_p, csrsrc_p, EE);

    dim3 ggrid((NN + BM - 1) / BM, HC / BN, 4);
    int attn_blocks = (NN + 7) / 8;

    // ---- layer 0 (input x, K=128) ----
    {
        GemmPtrs P;
        P.W[0] = Wq0; P.W[1] = Wk0; P.W[2] = Wv0; P.W[3] = Ws0;
        P.b[0] = bq0; P.b[1] = bk0; P.b[2] = bv0; P.b[3] = bs0;
        P.C[0] = q_p; P.C[1] = kb_p; P.C[2] = vb_p; P.C[3] = skip_p;
        P.bf16_mask = 0b0110;
        gemm4_tf32_kernel<<<ggrid, 256>>>(x, IN_F, P, NN);
        attn_kernel<<<attn_blocks, 256>>>(q_p, kb_p, vb_p, skip_p, rowptr_p, csrsrc_p, h_p, NN);
    }

    // ---- layers 1..3 (input g_h, K=256) ----
    for (int l = 0; l < NLAYERS - 1; l++) {
        GemmPtrs P;
        size_t wo = (size_t)l * HC * HC;
        size_t bo = (size_t)l * HC;
        P.W[0] = Wq + wo; P.W[1] = Wk + wo; P.W[2] = Wv + wo; P.W[3] = Ws + wo;
        P.b[0] = bq + bo; P.b[1] = bk + bo; P.b[2] = bv + bo; P.b[3] = bs + bo;
        P.C[0] = q_p; P.C[1] = kb_p; P.C[2] = vb_p; P.C[3] = skip_p;
        P.bf16_mask = 0b0110;
        gemm4_tf32_kernel<<<ggrid, 256>>>(h_p, HC, P, NN);
        attn_kernel<<<attn_blocks, 256>>>(q_p, kb_p, vb_p, skip_p, rowptr_p, csrsrc_p, h_p, NN);
    }

    // ---- global mean pool + FC ----
    zero_f_kernel<<<(GG * HC + 255) / 256, 256>>>(pooled_p, GG * HC);
    zero_i_kernel<<<1, 64>>>(gcnt_p, GG);
    pool_cnt_kernel<<<(NN + 255) / 256, 256>>>(batch, gcnt_p, NN);
    pool_sum_kernel<<<(NN + POOL_NODES - 1) / POOL_NODES, 256>>>(h_p, batch, pooled_p, NN);
    fc_kernel<<<GG, OUTF>>>(pooled_p, gcnt_p, Wfc, bfc, out);
}

// round 8
// speedup vs baseline: 1.9953x; 1.0537x over previous
#include <cuda_runtime.h>
#include <cuda_bf16.h>
#include <cstdint>

#define NN 50000
#define EE 800000
#define IN_F 128
#define HC 256
#define NHEAD 8
#define CDIM 32
#define GG 64
#define OUTF 64
#define NLAYERS 4

// ---------------- scratch (device globals; no allocation allowed) ----------------
__device__ float g_q[(size_t)NN * HC];
__device__ __nv_bfloat16 g_kb[(size_t)NN * HC];
__device__ __nv_bfloat16 g_vb[(size_t)NN * HC];
__device__ float g_skip[(size_t)NN * HC];
__device__ float g_h[(size_t)NN * HC];
__device__ int   g_deg[NN];
__device__ int   g_rowptr[NN + 1];
__device__ int   g_cursor[NN];
__device__ int   g_csrsrc[EE];
__device__ float g_pooled[GG * HC];
__device__ int   g_gcnt[GG];

// ---------------- small utility kernels ----------------
__global__ void zero_i_kernel(int* p, int n) {
    int i = blockIdx.x * blockDim.x + threadIdx.x;
    if (i < n) p[i] = 0;
}
__global__ void zero_f_kernel(float* p, int n) {
    int i = blockIdx.x * blockDim.x + threadIdx.x;
    if (i < n) p[i] = 0.0f;
}

// ---------------- CSR build ----------------
__global__ void hist_kernel(const int* __restrict__ dst, int* __restrict__ deg, int e) {
    int i = blockIdx.x * blockDim.x + threadIdx.x;
    if (i < e) atomicAdd(&deg[dst[i]], 1);
}

__global__ void scan_kernel(const int* __restrict__ deg, int* __restrict__ rowptr, int n) {
    __shared__ int sh[1024];
    __shared__ int carry;
    int tid = threadIdx.x;
    if (tid == 0) { carry = 0; rowptr[0] = 0; }
    __syncthreads();
    for (int base = 0; base < n; base += 1024) {
        int i = base + tid;
        sh[tid] = (i < n) ? deg[i] : 0;
        __syncthreads();
        for (int off = 1; off < 1024; off <<= 1) {
            int t = (tid >= off) ? sh[tid - off] : 0;
            __syncthreads();
            sh[tid] += t;
            __syncthreads();
        }
        int c = carry;
        if (i < n) rowptr[i + 1] = sh[tid] + c;
        __syncthreads();
        if (tid == 0) carry = c + sh[1023];
        __syncthreads();
    }
}

__global__ void cursor_init_kernel(const int* __restrict__ rowptr, int* __restrict__ cur, int n) {
    int i = blockIdx.x * blockDim.x + threadIdx.x;
    if (i < n) cur[i] = rowptr[i];
}

__global__ void scatter_kernel(const int* __restrict__ src, const int* __restrict__ dst,
                               int* __restrict__ cur, int* __restrict__ csrsrc, int e) {
    int i = blockIdx.x * blockDim.x + threadIdx.x;
    if (i < e) {
        int d = dst[i];
        int pos = atomicAdd(&cur[d], 1);
        csrsrc[pos] = src[i];
    }
}

// ---------------- tf32 tensor-core GEMM, smem double-buffered ----------------
struct GemmPtrs {
    const float* W[4];
    const float* b[4];
    void* C[4];
    int bf16_mask;
};

#define BM 128
#define BN 128
#define BK 32
#define APITCH 136
#define BPITCH 136
#define ASZ (BK * APITCH)
#define BSZ (BK * BPITCH)
#define GEMM_SMEM (2 * (ASZ + BSZ) * 4)

__device__ __forceinline__ float to_tf32(float x) {
    uint32_t u;
    asm("cvt.rna.tf32.f32 %0, %1;" : "=r"(u) : "f"(x));
    return __uint_as_float(u);
}

__device__ __forceinline__ void mma_tf32(float* d, const uint32_t* a, const uint32_t* b) {
    asm volatile(
        "mma.sync.aligned.m16n8k8.row.col.f32.tf32.tf32.f32 "
        "{%0,%1,%2,%3}, {%4,%5,%6,%7}, {%8,%9}, {%0,%1,%2,%3};"
        : "+f"(d[0]), "+f"(d[1]), "+f"(d[2]), "+f"(d[3])
        : "r"(a[0]), "r"(a[1]), "r"(a[2]), "r"(a[3]), "r"(b[0]), "r"(b[1]));
}

__global__ __launch_bounds__(256) void gemm4_tf32_kernel(const float* __restrict__ A, int K,
                                                         GemmPtrs P, int M) {
    const float* __restrict__ W = P.W[blockIdx.z];
    const float* __restrict__ bias = P.b[blockIdx.z];
    bool out_bf16 = (P.bf16_mask >> blockIdx.z) & 1;
    float* __restrict__ Cf = (float*)P.C[blockIdx.z];
    __nv_bfloat16* __restrict__ Cb = (__nv_bfloat16*)P.C[blockIdx.z];

    extern __shared__ float sm[];
    float* AsBase = sm;                 // 2 * ASZ
    float* BsBase = sm + 2 * ASZ;       // 2 * BSZ

    int t = threadIdx.x;
    int wid = t >> 5, lane = t & 31;
    int gid = lane >> 2, tig = lane & 3;
    int warpM = wid & 3;
    int warpN = wid >> 2;
    int m0 = blockIdx.x * BM;
    int n0 = blockIdx.y * BN;

    float acc[2][8][4];
#pragma unroll
    for (int mt = 0; mt < 2; mt++)
#pragma unroll
        for (int nt = 0; nt < 8; nt++)
#pragma unroll
            for (int j = 0; j < 4; j++) acc[mt][nt][j] = 0.0f;

    float4 pa[4], pb[4];
    int ntiles = K / BK;

    // prefetch tile 0 into regs
#pragma unroll
    for (int u = 0; u < 4; u++) {
        int f = t + u * 256;
        int r = f >> 3, c4 = f & 7;
        int gm = m0 + r;
        pa[u] = (gm < M) ? *(const float4*)(A + (size_t)gm * K + c4 * 4)
                         : make_float4(0.f, 0.f, 0.f, 0.f);
        int kr = f >> 5, bc4 = f & 31;
        pb[u] = *(const float4*)(W + (size_t)kr * HC + n0 + bc4 * 4);
    }
    // store tile 0 into buffer 0
#pragma unroll
    for (int u = 0; u < 4; u++) {
        int f = t + u * 256;
        int r = f >> 3, c4 = f & 7;
        AsBase[(c4 * 4 + 0) * APITCH + r] = to_tf32(pa[u].x);
        AsBase[(c4 * 4 + 1) * APITCH + r] = to_tf32(pa[u].y);
        AsBase[(c4 * 4 + 2) * APITCH + r] = to_tf32(pa[u].z);
        AsBase[(c4 * 4 + 3) * APITCH + r] = to_tf32(pa[u].w);
        int kr = f >> 5, bc4 = f & 31;
        BsBase[kr * BPITCH + bc4 * 4 + 0] = to_tf32(pb[u].x);
        BsBase[kr * BPITCH + bc4 * 4 + 1] = to_tf32(pb[u].y);
        BsBase[kr * BPITCH + bc4 * 4 + 2] = to_tf32(pb[u].z);
        BsBase[kr * BPITCH + bc4 * 4 + 3] = to_tf32(pb[u].w);
    }
    __syncthreads();

    for (int tile = 0; tile < ntiles; tile++) {
        int cur = tile & 1;
        const float* As = AsBase + cur * ASZ;
        const float* Bs = BsBase + cur * BSZ;
        bool have_next = (tile + 1 < ntiles);

        // issue global loads for next tile (consumed after the mma section)
        if (have_next) {
            int k0 = (tile + 1) * BK;
#pragma unroll
            for (int u = 0; u < 4; u++) {
                int f = t + u * 256;
                int r = f >> 3, c4 = f & 7;
                int gm = m0 + r;
                pa[u] = (gm < M) ? *(const float4*)(A + (size_t)gm * K + k0 + c4 * 4)
                                 : make_float4(0.f, 0.f, 0.f, 0.f);
                int kr = f >> 5, bc4 = f & 31;
                pb[u] = *(const float4*)(W + (size_t)(k0 + kr) * HC + n0 + bc4 * 4);
            }
        }

#pragma unroll
        for (int ks = 0; ks < 4; ks++) {
            int kb = ks * 8;
            uint32_t a[2][4];
#pragma unroll
            for (int mt = 0; mt < 2; mt++) {
                int m = warpM * 32 + mt * 16 + gid;
                a[mt][0] = __float_as_uint(As[(kb + tig) * APITCH + m]);
                a[mt][1] = __float_as_uint(As[(kb + tig) * APITCH + m + 8]);
                a[mt][2] = __float_as_uint(As[(kb + tig + 4) * APITCH + m]);
                a[mt][3] = __float_as_uint(As[(kb + tig + 4) * APITCH + m + 8]);
            }
            uint32_t b[8][2];
#pragma unroll
            for (int nt = 0; nt < 8; nt++) {
                int n = warpN * 64 + nt * 8 + gid;
                b[nt][0] = __float_as_uint(Bs[(kb + tig) * BPITCH + n]);
                b[nt][1] = __float_as_uint(Bs[(kb + tig + 4) * BPITCH + n]);
            }
#pragma unroll
            for (int mt = 0; mt < 2; mt++)
#pragma unroll
                for (int nt = 0; nt < 8; nt++) mma_tf32(acc[mt][nt], a[mt], b[nt]);
        }

        // store next tile into the other buffer (safe: the last reads of that
        // buffer completed before the barrier that ended the previous iteration)
        if (have_next) {
            float* Asn = AsBase + (cur ^ 1) * ASZ;
            float* Bsn = BsBase + (cur ^ 1) * BSZ;
#pragma unroll
            for (int u = 0; u < 4; u++) {
                int f = t + u * 256;
                int r = f >> 3, c4 = f & 7;
                Asn[(c4 * 4 + 0) * APITCH + r] = to_tf32(pa[u].x);
                Asn[(c4 * 4 + 1) * APITCH + r] = to_tf32(pa[u].y);
                Asn[(c4 * 4 + 2) * APITCH + r] = to_tf32(pa[u].z);
                Asn[(c4 * 4 + 3) * APITCH + r] = to_tf32(pa[u].w);
                int kr = f >> 5, bc4 = f & 31;
                Bsn[kr * BPITCH + bc4 * 4 + 0] = to_tf32(pb[u].x);
                Bsn[kr * BPITCH + bc4 * 4 + 1] = to_tf32(pb[u].y);
                Bsn[kr * BPITCH + bc4 * 4 + 2] = to_tf32(pb[u].z);
                Bsn[kr * BPITCH + bc4 * 4 + 3] = to_tf32(pb[u].w);
            }
        }
        __syncthreads();
    }

    // epilogue
#pragma unroll
    for (int mt = 0; mt < 2; mt++) {
#pragma unroll
        for (int nt = 0; nt < 8; nt++) {
            int n = n0 + warpN * 64 + nt * 8 + tig * 2;
            float b0 = bias[n];
            float b1 = bias[n + 1];
            int row0 = m0 + warpM * 32 + mt * 16 + gid;
            int row1 = row0 + 8;
            float v00 = acc[mt][nt][0] + b0, v01 = acc[mt][nt][1] + b1;
            float v10 = acc[mt][nt][2] + b0, v11 = acc[mt][nt][3] + b1;
            if (out_bf16) {
                if (row0 < M)
                    *(__nv_bfloat162*)(Cb + (size_t)row0 * HC + n) = __floats2bfloat162_rn(v00, v01);
                if (row1 < M)
                    *(__nv_bfloat162*)(Cb + (size_t)row1 * HC + n) = __floats2bfloat162_rn(v10, v11);
            } else {
                if (row0 < M) *(float2*)(Cf + (size_t)row0 * HC + n) = make_float2(v00, v01);
                if (row1 < M) *(float2*)(Cf + (size_t)row1 * HC + n) = make_float2(v10, v11);
            }
        }
    }
}

// ---------------- attention: one warp per dst node, 2-way ILP streaming softmax ----------------
__global__ __launch_bounds__(256) void attn_kernel(
    const float* __restrict__ q, const __nv_bfloat16* __restrict__ kb,
    const __nv_bfloat16* __restrict__ vb, const float* __restrict__ skp,
    const int* __restrict__ rowptr, const int* __restrict__ srcs,
    float* __restrict__ hout, int n_nodes) {

    int warp = (blockIdx.x * blockDim.x + threadIdx.x) >> 5;
    int lane = threadIdx.x & 31;
    if (warp >= n_nodes) return;

    // lane l owns channels [8l, 8l+8) -> head l/4
    const float4* qp = (const float4*)(q + (size_t)warp * HC);
    float4 q1 = qp[lane * 2];
    float4 q2 = qp[lane * 2 + 1];

    const float scale = 0.17677669529663687f;  // 1/sqrt(32)

    // two independent softmax streams (A: even edges, B: odd edges)
    float mA = -1e30f, sA = 0.0f;
    float aA0 = 0.f, aA1 = 0.f, aA2 = 0.f, aA3 = 0.f, aA4 = 0.f, aA5 = 0.f, aA6 = 0.f, aA7 = 0.f;
    float mB = -1e30f, sB = 0.0f;
    float aB0 = 0.f, aB1 = 0.f, aB2 = 0.f, aB3 = 0.f, aB4 = 0.f, aB5 = 0.f, aB6 = 0.f, aB7 = 0.f;

    int e0 = rowptr[warp];
    int e1 = rowptr[warp + 1];

    // current pair + prefetched next pair
    uint4 kA, vA, kB, vB;
    if (e0 < e1) {
        int s = srcs[e0];
        kA = *(const uint4*)(kb + (size_t)s * HC + lane * 8);
        vA = *(const uint4*)(vb + (size_t)s * HC + lane * 8);
        if (e0 + 1 < e1) {
            int s2 = srcs[e0 + 1];
            kB = *(const uint4*)(kb + (size_t)s2 * HC + lane * 8);
            vB = *(const uint4*)(vb + (size_t)s2 * HC + lane * 8);
        }
    }

    for (int e = e0; e < e1; e += 2) {
        uint4 ckA = kA, cvA = vA, ckB = kB, cvB = vB;
        bool haveB = (e + 1 < e1);
        // prefetch next pair (overlaps both dependent chains below)
        if (e + 2 < e1) {
            int sa = srcs[e + 2];
            kA = *(const uint4*)(kb + (size_t)sa * HC + lane * 8);
            vA = *(const uint4*)(vb + (size_t)sa * HC + lane * 8);
            if (e + 3 < e1) {
                int sb = srcs[e + 3];
                kB = *(const uint4*)(kb + (size_t)sb * HC + lane * 8);
                vB = *(const uint4*)(vb + (size_t)sb * HC + lane * 8);
            }
        }

        // ---- stream A ----
        {
            float2 k0 = __bfloat1622float2(*(__nv_bfloat162*)&ckA.x);
            float2 k1 = __bfloat1622float2(*(__nv_bfloat162*)&ckA.y);
            float2 k2 = __bfloat1622float2(*(__nv_bfloat162*)&ckA.z);
            float2 k3 = __bfloat1622float2(*(__nv_bfloat162*)&ckA.w);
            float d = q1.x * k0.x + q1.y * k0.y + q1.z * k1.x + q1.w * k1.y +
                      q2.x * k2.x + q2.y * k2.y + q2.z * k3.x + q2.w * k3.y;
            d += __shfl_xor_sync(0xffffffffu, d, 1);
            d += __shfl_xor_sync(0xffffffffu, d, 2);
            float logit = d * scale;
            float mn = fmaxf(mA, logit);
            float corr = __expf(mA - mn);
            float p = __expf(logit - mn);
            mA = mn;
            sA = sA * corr + p;
            float2 v0 = __bfloat1622float2(*(__nv_bfloat162*)&cvA.x);
            float2 v1 = __bfloat1622float2(*(__nv_bfloat162*)&cvA.y);
            float2 v2 = __bfloat1622float2(*(__nv_bfloat162*)&cvA.z);
            float2 v3 = __bfloat1622float2(*(__nv_bfloat162*)&cvA.w);
            aA0 = aA0 * corr + p * v0.x;
            aA1 = aA1 * corr + p * v0.y;
            aA2 = aA2 * corr + p * v1.x;
            aA3 = aA3 * corr + p * v1.y;
            aA4 = aA4 * corr + p * v2.x;
            aA5 = aA5 * corr + p * v2.y;
            aA6 = aA6 * corr + p * v3.x;
            aA7 = aA7 * corr + p * v3.y;
        }
        // ---- stream B ----
        if (haveB) {
            float2 k0 = __bfloat1622float2(*(__nv_bfloat162*)&ckB.x);
            float2 k1 = __bfloat1622float2(*(__nv_bfloat162*)&ckB.y);
            float2 k2 = __bfloat1622float2(*(__nv_bfloat162*)&ckB.z);
            float2 k3 = __bfloat1622float2(*(__nv_bfloat162*)&ckB.w);
            float d = q1.x * k0.x + q1.y * k0.y + q1.z * k1.x + q1.w * k1.y +
                      q2.x * k2.x + q2.y * k2.y + q2.z * k3.x + q2.w * k3.y;
            d += __shfl_xor_sync(0xffffffffu, d, 1);
            d += __shfl_xor_sync(0xffffffffu, d, 2);
            float logit = d * scale;
            float mn = fmaxf(mB, logit);
            float corr = __expf(mB - mn);
            float p = __expf(logit - mn);
            mB = mn;
            sB = sB * corr + p;
            float2 v0 = __bfloat1622float2(*(__nv_bfloat162*)&cvB.x);
            float2 v1 = __bfloat1622float2(*(__nv_bfloat162*)&cvB.y);
            float2 v2 = __bfloat1622float2(*(__nv_bfloat162*)&cvB.z);
            float2 v3 = __bfloat1622float2(*(__nv_bfloat162*)&cvB.w);
            aB0 = aB0 * corr + p * v0.x;
            aB1 = aB1 * corr + p * v0.y;
            aB2 = aB2 * corr + p * v1.x;
            aB3 = aB3 * corr + p * v1.y;
            aB4 = aB4 * corr + p * v2.x;
            aB5 = aB5 * corr + p * v2.y;
            aB6 = aB6 * corr + p * v3.x;
            aB7 = aB7 * corr + p * v3.y;
        }
    }

    // merge streams (exact flash merge; sB=0 if no odd edges so B contributes nothing)
    float mn = fmaxf(mA, mB);
    float cA = __expf(mA - mn);
    float cB = __expf(mB - mn);
    float ssum = sA * cA + sB * cB;
    float acc0 = aA0 * cA + aB0 * cB;
    float acc1 = aA1 * cA + aB1 * cB;
    float acc2 = aA2 * cA + aB2 * cB;
    float acc3 = aA3 * cA + aB3 * cB;
    float acc4 = aA4 * cA + aB4 * cB;
    float acc5 = aA5 * cA + aB5 * cB;
    float acc6 = aA6 * cA + aB6 * cB;
    float acc7 = aA7 * cA + aB7 * cB;

    float inv = 1.0f / (ssum + 1e-16f);
    const float4* sp = (const float4*)(skp + (size_t)warp * HC);
    float4 s1 = sp[lane * 2];
    float4 s2 = sp[lane * 2 + 1];
    float4 o1, o2;
    o1.x = fmaxf(acc0 * inv + s1.x, 0.f);
    o1.y = fmaxf(acc1 * inv + s1.y, 0.f);
    o1.z = fmaxf(acc2 * inv + s1.z, 0.f);
    o1.w = fmaxf(acc3 * inv + s1.w, 0.f);
    o2.x = fmaxf(acc4 * inv + s2.x, 0.f);
    o2.y = fmaxf(acc5 * inv + s2.y, 0.f);
    o2.z = fmaxf(acc6 * inv + s2.z, 0.f);
    o2.w = fmaxf(acc7 * inv + s2.w, 0.f);
    float4* op = (float4*)(hout + (size_t)warp * HC);
    op[lane * 2] = o1;
    op[lane * 2 + 1] = o2;
}

// ---------------- pooling + FC ----------------
__global__ void pool_cnt_kernel(const int* __restrict__ batch, int* __restrict__ cnt, int n) {
    int i = blockIdx.x * blockDim.x + threadIdx.x;
    if (i < n) atomicAdd(&cnt[batch[i]], 1);
}

#define POOL_NODES 128
__global__ __launch_bounds__(256) void pool_sum_kernel(const float* __restrict__ h,
                                                       const int* __restrict__ batch,
                                                       float* __restrict__ pooled, int n) {
    int c = threadIdx.x;
    int node0 = blockIdx.x * POOL_NODES;
    int nodeEnd = min(node0 + POOL_NODES, n);
    int curg = batch[node0];
    float accu = 0.0f;
    for (int node = node0; node < nodeEnd; node++) {
        int g = batch[node];
        if (g != curg) {
            atomicAdd(&pooled[curg * HC + c], accu);
            accu = 0.0f;
            curg = g;
        }
        accu += h[(size_t)node * HC + c];
    }
    atomicAdd(&pooled[curg * HC + c], accu);
}

__global__ void fc_kernel(const float* __restrict__ pooled, const int* __restrict__ cnt,
                          const float* __restrict__ Wfc, const float* __restrict__ bfc,
                          float* __restrict__ out) {
    int g = blockIdx.x;
    int o = threadIdx.x;  // 64
    __shared__ float pr[HC];
    float invc = 1.0f / fmaxf((float)cnt[g], 1.0f);
    for (int c = o; c < HC; c += 64) pr[c] = pooled[g * HC + c] * invc;
    __syncthreads();
    float accu = bfc[o];
#pragma unroll 8
    for (int c = 0; c < HC; c++) accu += pr[c] * Wfc[c * OUTF + o];
    out[g * OUTF + o] = accu;
}

// ---------------- host orchestration ----------------
extern "C" void kernel_launch(void* const* d_in, const int* in_sizes, int n_in,
                              void* d_out, int out_size) {
    const float* x = (const float*)d_in[0];
    const int* edge = (const int*)d_in[1];   // [2,E]: row0=src, row1=dst
    const int* batch = (const int*)d_in[2];
    const float* Wq0 = (const float*)d_in[3];
    const float* bq0 = (const float*)d_in[4];
    const float* Wk0 = (const float*)d_in[5];
    const float* bk0 = (const float*)d_in[6];
    const float* Wv0 = (const float*)d_in[7];
    const float* bv0 = (const float*)d_in[8];
    const float* Ws0 = (const float*)d_in[9];
    const float* bs0 = (const float*)d_in[10];
    const float* Wq = (const float*)d_in[11];
    const float* bq = (const float*)d_in[12];
    const float* Wk = (const float*)d_in[13];
    const float* bk = (const float*)d_in[14];
    const float* Wv = (const float*)d_in[15];
    const float* bv = (const float*)d_in[16];
    const float* Ws = (const float*)d_in[17];
    const float* bs = (const float*)d_in[18];
    const float* Wfc = (const float*)d_in[19];
    const float* bfc = (const float*)d_in[20];
    float* out = (float*)d_out;

    const int* srcp = edge;
    const int* dstp = edge + EE;

    float *q_p, *skip_p, *h_p, *pooled_p;
    __nv_bfloat16 *kb_p, *vb_p;
    int *deg_p, *rowptr_p, *cursor_p, *csrsrc_p, *gcnt_p;
    cudaGetSymbolAddress((void**)&q_p, g_q);
    cudaGetSymbolAddress((void**)&kb_p, g_kb);
    cudaGetSymbolAddress((void**)&vb_p, g_vb);
    cudaGetSymbolAddress((void**)&skip_p, g_skip);
    cudaGetSymbolAddress((void**)&h_p, g_h);
    cudaGetSymbolAddress((void**)&deg_p, g_deg);
    cudaGetSymbolAddress((void**)&rowptr_p, g_rowptr);
    cudaGetSymbolAddress((void**)&cursor_p, g_cursor);
    cudaGetSymbolAddress((void**)&csrsrc_p, g_csrsrc);
    cudaGetSymbolAddress((void**)&pooled_p, g_pooled);
    cudaGetSymbolAddress((void**)&gcnt_p, g_gcnt);

    // idempotent; no static guards (harness contract forbids them)
    cudaFuncSetAttribute(gemm4_tf32_kernel,
                         cudaFuncAttributeMaxDynamicSharedMemorySize, GEMM_SMEM);

    // ---- CSR build (edges identical across layers; build once) ----
    zero_i_kernel<<<(NN + 255) / 256, 256>>>(deg_p, NN);
    hist_kernel<<<(EE + 255) / 256, 256>>>(dstp, deg_p, EE);
    scan_kernel<<<1, 1024>>>(deg_p, rowptr_p, NN);
    cursor_init_kernel<<<(NN + 255) / 256, 256>>>(rowptr_p, cursor_p, NN);
    scatter_kernel<<<(EE + 255) / 256, 256>>>(srcp, dstp, cursor_p, csrsrc_p, EE);

    dim3 ggrid((NN + BM - 1) / BM, HC / BN, 4);
    int attn_blocks = (NN + 7) / 8;

    // ---- layer 0 (input x, K=128) ----
    {
        GemmPtrs P;
        P.W[0] = Wq0; P.W[1] = Wk0; P.W[2] = Wv0; P.W[3] = Ws0;
        P.b[0] = bq0; P.b[1] = bk0; P.b[2] = bv0; P.b[3] = bs0;
        P.C[0] = q_p; P.C[1] = kb_p; P.C[2] = vb_p; P.C[3] = skip_p;
        P.bf16_mask = 0b0110;
        gemm4_tf32_kernel<<<ggrid, 256, GEMM_SMEM>>>(x, IN_F, P, NN);
        attn_kernel<<<attn_blocks, 256>>>(q_p, kb_p, vb_p, skip_p, rowptr_p, csrsrc_p, h_p, NN);
    }

    // ---- layers 1..3 (input g_h, K=256) ----
    for (int l = 0; l < NLAYERS - 1; l++) {
        GemmPtrs P;
        size_t wo = (size_t)l * HC * HC;
        size_t bo = (size_t)l * HC;
        P.W[0] = Wq + wo; P.W[1] = Wk + wo; P.W[2] = Wv + wo; P.W[3] = Ws + wo;
        P.b[0] = bq + bo; P.b[1] = bk + bo; P.b[2] = bv + bo; P.b[3] = bs + bo;
        P.C[0] = q_p; P.C[1] = kb_p; P.C[2] = vb_p; P.C[3] = skip_p;
        P.bf16_mask = 0b0110;
        gemm4_tf32_kernel<<<ggrid, 256, GEMM_SMEM>>>(h_p, HC, P, NN);
        attn_kernel<<<attn_blocks, 256>>>(q_p, kb_p, vb_p, skip_p, rowptr_p, csrsrc_p, h_p, NN);
    }

    // ---- global mean pool + FC ----
    zero_f_kernel<<<(GG * HC + 255) / 256, 256>>>(pooled_p, GG * HC);
    zero_i_kernel<<<1, 64>>>(gcnt_p, GG);
    pool_cnt_kernel<<<(NN + 255) / 256, 256>>>(batch, gcnt_p, NN);
    pool_sum_kernel<<<(NN + POOL_NODES - 1) / POOL_NODES, 256>>>(h_p, batch, pooled_p, NN);
    fc_kernel<<<GG, OUTF>>>(pooled_p, gcnt_p, Wfc, bfc, out);
}

// round 9
// speedup vs baseline: 1.9996x; 1.0021x over previous
#include <cuda_runtime.h>
#include <cuda_bf16.h>
#include <cstdint>

#define NN 50000
#define EE 800000
#define IN_F 128
#define HC 256
#define NHEAD 8
#define CDIM 32
#define GG 64
#define OUTF 64
#define NLAYERS 4

// ---------------- scratch (device globals; no allocation allowed) ----------------
__device__ float g_q[(size_t)NN * HC];
__device__ __nv_bfloat16 g_kb[(size_t)NN * HC];
__device__ __nv_bfloat16 g_vb[(size_t)NN * HC];
__device__ float g_skip[(size_t)NN * HC];
__device__ float g_h[(size_t)NN * HC];
__device__ int   g_deg[NN];
__device__ int   g_rowptr[NN + 1];
__device__ int   g_cursor[NN];
__device__ int   g_csrsrc[EE];
__device__ float g_pooled[GG * HC];
__device__ int   g_gcnt[GG];

// ---------------- small utility kernels ----------------
__global__ void zero_i_kernel(int* p, int n) {
    int i = blockIdx.x * blockDim.x + threadIdx.x;
    if (i < n) p[i] = 0;
}
__global__ void zero_f_kernel(float* p, int n) {
    int i = blockIdx.x * blockDim.x + threadIdx.x;
    if (i < n) p[i] = 0.0f;
}

// ---------------- CSR build ----------------
__global__ void hist_kernel(const int* __restrict__ dst, int* __restrict__ deg, int e) {
    int i = blockIdx.x * blockDim.x + threadIdx.x;
    if (i < e) atomicAdd(&deg[dst[i]], 1);
}

__global__ void scan_kernel(const int* __restrict__ deg, int* __restrict__ rowptr, int n) {
    __shared__ int sh[1024];
    __shared__ int carry;
    int tid = threadIdx.x;
    if (tid == 0) { carry = 0; rowptr[0] = 0; }
    __syncthreads();
    for (int base = 0; base < n; base += 1024) {
        int i = base + tid;
        sh[tid] = (i < n) ? deg[i] : 0;
        __syncthreads();
        for (int off = 1; off < 1024; off <<= 1) {
            int t = (tid >= off) ? sh[tid - off] : 0;
            __syncthreads();
            sh[tid] += t;
            __syncthreads();
        }
        int c = carry;
        if (i < n) rowptr[i + 1] = sh[tid] + c;
        __syncthreads();
        if (tid == 0) carry = c + sh[1023];
        __syncthreads();
    }
}

__global__ void cursor_init_kernel(const int* __restrict__ rowptr, int* __restrict__ cur, int n) {
    int i = blockIdx.x * blockDim.x + threadIdx.x;
    if (i < n) cur[i] = rowptr[i];
}

__global__ void scatter_kernel(const int* __restrict__ src, const int* __restrict__ dst,
                               int* __restrict__ cur, int* __restrict__ csrsrc, int e) {
    int i = blockIdx.x * blockDim.x + threadIdx.x;
    if (i < e) {
        int d = dst[i];
        int pos = atomicAdd(&cur[d], 1);
        csrsrc[pos] = src[i];
    }
}

// ---------------- tf32 tensor-core GEMM, smem double-buffered ----------------
struct GemmPtrs {
    const float* W[4];
    const float* b[4];
    void* C[4];
    int bf16_mask;
};

#define BM 128
#define BN 128
#define BK 32
#define APITCH 136
#define BPITCH 136
#define ASZ (BK * APITCH)
#define BSZ (BK * BPITCH)
#define GEMM_SMEM (2 * (ASZ + BSZ) * 4)

__device__ __forceinline__ float to_tf32(float x) {
    uint32_t u;
    asm("cvt.rna.tf32.f32 %0, %1;" : "=r"(u) : "f"(x));
    return __uint_as_float(u);
}

__device__ __forceinline__ void mma_tf32(float* d, const uint32_t* a, const uint32_t* b) {
    asm volatile(
        "mma.sync.aligned.m16n8k8.row.col.f32.tf32.tf32.f32 "
        "{%0,%1,%2,%3}, {%4,%5,%6,%7}, {%8,%9}, {%0,%1,%2,%3};"
        : "+f"(d[0]), "+f"(d[1]), "+f"(d[2]), "+f"(d[3])
        : "r"(a[0]), "r"(a[1]), "r"(a[2]), "r"(a[3]), "r"(b[0]), "r"(b[1]));
}

__global__ __launch_bounds__(256) void gemm4_tf32_kernel(const float* __restrict__ A, int K,
                                                         GemmPtrs P, int M) {
    const float* __restrict__ W = P.W[blockIdx.z];
    const float* __restrict__ bias = P.b[blockIdx.z];
    bool out_bf16 = (P.bf16_mask >> blockIdx.z) & 1;
    float* __restrict__ Cf = (float*)P.C[blockIdx.z];
    __nv_bfloat16* __restrict__ Cb = (__nv_bfloat16*)P.C[blockIdx.z];

    extern __shared__ float sm[];
    float* AsBase = sm;                 // 2 * ASZ
    float* BsBase = sm + 2 * ASZ;       // 2 * BSZ

    int t = threadIdx.x;
    int wid = t >> 5, lane = t & 31;
    int gid = lane >> 2, tig = lane & 3;
    int warpM = wid & 3;
    int warpN = wid >> 2;
    int m0 = blockIdx.x * BM;
    int n0 = blockIdx.y * BN;

    float acc[2][8][4];
#pragma unroll
    for (int mt = 0; mt < 2; mt++)
#pragma unroll
        for (int nt = 0; nt < 8; nt++)
#pragma unroll
            for (int j = 0; j < 4; j++) acc[mt][nt][j] = 0.0f;

    float4 pa[4], pb[4];
    int ntiles = K / BK;

    // prefetch tile 0 into regs
#pragma unroll
    for (int u = 0; u < 4; u++) {
        int f = t + u * 256;
        int r = f >> 3, c4 = f & 7;
        int gm = m0 + r;
        pa[u] = (gm < M) ? *(const float4*)(A + (size_t)gm * K + c4 * 4)
                         : make_float4(0.f, 0.f, 0.f, 0.f);
        int kr = f >> 5, bc4 = f & 31;
        pb[u] = *(const float4*)(W + (size_t)kr * HC + n0 + bc4 * 4);
    }
    // store tile 0 into buffer 0
#pragma unroll
    for (int u = 0; u < 4; u++) {
        int f = t + u * 256;
        int r = f >> 3, c4 = f & 7;
        AsBase[(c4 * 4 + 0) * APITCH + r] = to_tf32(pa[u].x);
        AsBase[(c4 * 4 + 1) * APITCH + r] = to_tf32(pa[u].y);
        AsBase[(c4 * 4 + 2) * APITCH + r] = to_tf32(pa[u].z);
        AsBase[(c4 * 4 + 3) * APITCH + r] = to_tf32(pa[u].w);
        int kr = f >> 5, bc4 = f & 31;
        BsBase[kr * BPITCH + bc4 * 4 + 0] = to_tf32(pb[u].x);
        BsBase[kr * BPITCH + bc4 * 4 + 1] = to_tf32(pb[u].y);
        BsBase[kr * BPITCH + bc4 * 4 + 2] = to_tf32(pb[u].z);
        BsBase[kr * BPITCH + bc4 * 4 + 3] = to_tf32(pb[u].w);
    }
    __syncthreads();

    for (int tile = 0; tile < ntiles; tile++) {
        int cur = tile & 1;
        const float* As = AsBase + cur * ASZ;
        const float* Bs = BsBase + cur * BSZ;
        bool have_next = (tile + 1 < ntiles);

        // issue global loads for next tile (consumed after the mma section)
        if (have_next) {
            int k0 = (tile + 1) * BK;
#pragma unroll
            for (int u = 0; u < 4; u++) {
                int f = t + u * 256;
                int r = f >> 3, c4 = f & 7;
                int gm = m0 + r;
                pa[u] = (gm < M) ? *(const float4*)(A + (size_t)gm * K + k0 + c4 * 4)
                                 : make_float4(0.f, 0.f, 0.f, 0.f);
                int kr = f >> 5, bc4 = f & 31;
                pb[u] = *(const float4*)(W + (size_t)(k0 + kr) * HC + n0 + bc4 * 4);
            }
        }

#pragma unroll
        for (int ks = 0; ks < 4; ks++) {
            int kb = ks * 8;
            uint32_t a[2][4];
#pragma unroll
            for (int mt = 0; mt < 2; mt++) {
                int m = warpM * 32 + mt * 16 + gid;
                a[mt][0] = __float_as_uint(As[(kb + tig) * APITCH + m]);
                a[mt][1] = __float_as_uint(As[(kb + tig) * APITCH + m + 8]);
                a[mt][2] = __float_as_uint(As[(kb + tig + 4) * APITCH + m]);
                a[mt][3] = __float_as_uint(As[(kb + tig + 4) * APITCH + m + 8]);
            }
            uint32_t b[8][2];
#pragma unroll
            for (int nt = 0; nt < 8; nt++) {
                int n = warpN * 64 + nt * 8 + gid;
                b[nt][0] = __float_as_uint(Bs[(kb + tig) * BPITCH + n]);
                b[nt][1] = __float_as_uint(Bs[(kb + tig + 4) * BPITCH + n]);
            }
#pragma unroll
            for (int mt = 0; mt < 2; mt++)
#pragma unroll
                for (int nt = 0; nt < 8; nt++) mma_tf32(acc[mt][nt], a[mt], b[nt]);
        }

        // store next tile into the other buffer (safe: the last reads of that
        // buffer completed before the barrier that ended the previous iteration)
        if (have_next) {
            float* Asn = AsBase + (cur ^ 1) * ASZ;
            float* Bsn = BsBase + (cur ^ 1) * BSZ;
#pragma unroll
            for (int u = 0; u < 4; u++) {
                int f = t + u * 256;
                int r = f >> 3, c4 = f & 7;
                Asn[(c4 * 4 + 0) * APITCH + r] = to_tf32(pa[u].x);
                Asn[(c4 * 4 + 1) * APITCH + r] = to_tf32(pa[u].y);
                Asn[(c4 * 4 + 2) * APITCH + r] = to_tf32(pa[u].z);
                Asn[(c4 * 4 + 3) * APITCH + r] = to_tf32(pa[u].w);
                int kr = f >> 5, bc4 = f & 31;
                Bsn[kr * BPITCH + bc4 * 4 + 0] = to_tf32(pb[u].x);
                Bsn[kr * BPITCH + bc4 * 4 + 1] = to_tf32(pb[u].y);
                Bsn[kr * BPITCH + bc4 * 4 + 2] = to_tf32(pb[u].z);
                Bsn[kr * BPITCH + bc4 * 4 + 3] = to_tf32(pb[u].w);
            }
        }
        __syncthreads();
    }

    // epilogue
#pragma unroll
    for (int mt = 0; mt < 2; mt++) {
#pragma unroll
        for (int nt = 0; nt < 8; nt++) {
            int n = n0 + warpN * 64 + nt * 8 + tig * 2;
            float b0 = bias[n];
            float b1 = bias[n + 1];
            int row0 = m0 + warpM * 32 + mt * 16 + gid;
            int row1 = row0 + 8;
            float v00 = acc[mt][nt][0] + b0, v01 = acc[mt][nt][1] + b1;
            float v10 = acc[mt][nt][2] + b0, v11 = acc[mt][nt][3] + b1;
            if (out_bf16) {
                if (row0 < M)
                    *(__nv_bfloat162*)(Cb + (size_t)row0 * HC + n) = __floats2bfloat162_rn(v00, v01);
                if (row1 < M)
                    *(__nv_bfloat162*)(Cb + (size_t)row1 * HC + n) = __floats2bfloat162_rn(v10, v11);
            } else {
                if (row0 < M) *(float2*)(Cf + (size_t)row0 * HC + n) = make_float2(v00, v01);
                if (row1 < M) *(float2*)(Cf + (size_t)row1 * HC + n) = make_float2(v10, v11);
            }
        }
    }
}

// ---------------- attention: one warp per dst node, 2-way ILP streaming softmax ----------------
__global__ __launch_bounds__(256) void attn_kernel(
    const float* __restrict__ q, const __nv_bfloat16* __restrict__ kb,
    const __nv_bfloat16* __restrict__ vb, const float* __restrict__ skp,
    const int* __restrict__ rowptr, const int* __restrict__ srcs,
    float* __restrict__ hout, int n_nodes) {

    int warp = (blockIdx.x * blockDim.x + threadIdx.x) >> 5;
    int lane = threadIdx.x & 31;
    if (warp >= n_nodes) return;

    // lane l owns channels [8l, 8l+8) -> head l/4
    const float4* qp = (const float4*)(q + (size_t)warp * HC);
    float4 q1 = qp[lane * 2];
    float4 q2 = qp[lane * 2 + 1];

    const float scale = 0.17677669529663687f;  // 1/sqrt(32)

    // two independent softmax streams (A: even edges, B: odd edges)
    float mA = -1e30f, sA = 0.0f;
    float aA0 = 0.f, aA1 = 0.f, aA2 = 0.f, aA3 = 0.f, aA4 = 0.f, aA5 = 0.f, aA6 = 0.f, aA7 = 0.f;
    float mB = -1e30f, sB = 0.0f;
    float aB0 = 0.f, aB1 = 0.f, aB2 = 0.f, aB3 = 0.f, aB4 = 0.f, aB5 = 0.f, aB6 = 0.f, aB7 = 0.f;

    int e0 = rowptr[warp];
    int e1 = rowptr[warp + 1];

    // current pair + prefetched next pair
    uint4 kA, vA, kB, vB;
    if (e0 < e1) {
        int s = srcs[e0];
        kA = *(const uint4*)(kb + (size_t)s * HC + lane * 8);
        vA = *(const uint4*)(vb + (size_t)s * HC + lane * 8);
        if (e0 + 1 < e1) {
            int s2 = srcs[e0 + 1];
            kB = *(const uint4*)(kb + (size_t)s2 * HC + lane * 8);
            vB = *(const uint4*)(vb + (size_t)s2 * HC + lane * 8);
        }
    }

    for (int e = e0; e < e1; e += 2) {
        uint4 ckA = kA, cvA = vA, ckB = kB, cvB = vB;
        bool haveB = (e + 1 < e1);
        // prefetch next pair (overlaps both dependent chains below)
        if (e + 2 < e1) {
            int sa = srcs[e + 2];
            kA = *(const uint4*)(kb + (size_t)sa * HC + lane * 8);
            vA = *(const uint4*)(vb + (size_t)sa * HC + lane * 8);
            if (e + 3 < e1) {
                int sb = srcs[e + 3];
                kB = *(const uint4*)(kb + (size_t)sb * HC + lane * 8);
                vB = *(const uint4*)(vb + (size_t)sb * HC + lane * 8);
            }
        }

        // ---- stream A ----
        {
            float2 k0 = __bfloat1622float2(*(__nv_bfloat162*)&ckA.x);
            float2 k1 = __bfloat1622float2(*(__nv_bfloat162*)&ckA.y);
            float2 k2 = __bfloat1622float2(*(__nv_bfloat162*)&ckA.z);
            float2 k3 = __bfloat1622float2(*(__nv_bfloat162*)&ckA.w);
            float d = q1.x * k0.x + q1.y * k0.y + q1.z * k1.x + q1.w * k1.y +
                      q2.x * k2.x + q2.y * k2.y + q2.z * k3.x + q2.w * k3.y;
            d += __shfl_xor_sync(0xffffffffu, d, 1);
            d += __shfl_xor_sync(0xffffffffu, d, 2);
            float logit = d * scale;
            float mn = fmaxf(mA, logit);
            float corr = __expf(mA - mn);
            float p = __expf(logit - mn);
            mA = mn;
            sA = sA * corr + p;
            float2 v0 = __bfloat1622float2(*(__nv_bfloat162*)&cvA.x);
            float2 v1 = __bfloat1622float2(*(__nv_bfloat162*)&cvA.y);
            float2 v2 = __bfloat1622float2(*(__nv_bfloat162*)&cvA.z);
            float2 v3 = __bfloat1622float2(*(__nv_bfloat162*)&cvA.w);
            aA0 = aA0 * corr + p * v0.x;
            aA1 = aA1 * corr + p * v0.y;
            aA2 = aA2 * corr + p * v1.x;
            aA3 = aA3 * corr + p * v1.y;
            aA4 = aA4 * corr + p * v2.x;
            aA5 = aA5 * corr + p * v2.y;
            aA6 = aA6 * corr + p * v3.x;
            aA7 = aA7 * corr + p * v3.y;
        }
        // ---- stream B ----
        if (haveB) {
            float2 k0 = __bfloat1622float2(*(__nv_bfloat162*)&ckB.x);
            float2 k1 = __bfloat1622float2(*(__nv_bfloat162*)&ckB.y);
            float2 k2 = __bfloat1622float2(*(__nv_bfloat162*)&ckB.z);
            float2 k3 = __bfloat1622float2(*(__nv_bfloat162*)&ckB.w);
            float d = q1.x * k0.x + q1.y * k0.y + q1.z * k1.x + q1.w * k1.y +
                      q2.x * k2.x + q2.y * k2.y + q2.z * k3.x + q2.w * k3.y;
            d += __shfl_xor_sync(0xffffffffu, d, 1);
            d += __shfl_xor_sync(0xffffffffu, d, 2);
            float logit = d * scale;
            float mn = fmaxf(mB, logit);
            float corr = __expf(mB - mn);
            float p = __expf(logit - mn);
            mB = mn;
            sB = sB * corr + p;
            float2 v0 = __bfloat1622float2(*(__nv_bfloat162*)&cvB.x);
            float2 v1 = __bfloat1622float2(*(__nv_bfloat162*)&cvB.y);
            float2 v2 = __bfloat1622float2(*(__nv_bfloat162*)&cvB.z);
            float2 v3 = __bfloat1622float2(*(__nv_bfloat162*)&cvB.w);
            aB0 = aB0 * corr + p * v0.x;
            aB1 = aB1 * corr + p * v0.y;
            aB2 = aB2 * corr + p * v1.x;
            aB3 = aB3 * corr + p * v1.y;
            aB4 = aB4 * corr + p * v2.x;
            aB5 = aB5 * corr + p * v2.y;
            aB6 = aB6 * corr + p * v3.x;
            aB7 = aB7 * corr + p * v3.y;
        }
    }

    // merge streams (exact flash merge; sB=0 if no odd edges so B contributes nothing)
    float mn = fmaxf(mA, mB);
    float cA = __expf(mA - mn);
    float cB = __expf(mB - mn);
    float ssum = sA * cA + sB * cB;
    float acc0 = aA0 * cA + aB0 * cB;
    float acc1 = aA1 * cA + aB1 * cB;
    float acc2 = aA2 * cA + aB2 * cB;
    float acc3 = aA3 * cA + aB3 * cB;
    float acc4 = aA4 * cA + aB4 * cB;
    float acc5 = aA5 * cA + aB5 * cB;
    float acc6 = aA6 * cA + aB6 * cB;
    float acc7 = aA7 * cA + aB7 * cB;

    float inv = 1.0f / (ssum + 1e-16f);
    const float4* sp = (const float4*)(skp + (size_t)warp * HC);
    float4 s1 = sp[lane * 2];
    float4 s2 = sp[lane * 2 + 1];
    float4 o1, o2;
    o1.x = fmaxf(acc0 * inv + s1.x, 0.f);
    o1.y = fmaxf(acc1 * inv + s1.y, 0.f);
    o1.z = fmaxf(acc2 * inv + s1.z, 0.f);
    o1.w = fmaxf(acc3 * inv + s1.w, 0.f);
    o2.x = fmaxf(acc4 * inv + s2.x, 0.f);
    o2.y = fmaxf(acc5 * inv + s2.y, 0.f);
    o2.z = fmaxf(acc6 * inv + s2.z, 0.f);
    o2.w = fmaxf(acc7 * inv + s2.w, 0.f);
    float4* op = (float4*)(hout + (size_t)warp * HC);
    op[lane * 2] = o1;
    op[lane * 2 + 1] = o2;
}

// ---------------- pooling + FC ----------------
__global__ void pool_cnt_kernel(const int* __restrict__ batch, int* __restrict__ cnt, int n) {
    int i = blockIdx.x * blockDim.x + threadIdx.x;
    if (i < n) atomicAdd(&cnt[batch[i]], 1);
}

#define POOL_NODES 128
__global__ __launch_bounds__(256) void pool_sum_kernel(const float* __restrict__ h,
                                                       const int* __restrict__ batch,
                                                       float* __restrict__ pooled, int n) {
    int c = threadIdx.x;
    int node0 = blockIdx.x * POOL_NODES;
    int nodeEnd = min(node0 + POOL_NODES, n);
    int curg = batch[node0];
    float accu = 0.0f;
    for (int node = node0; node < nodeEnd; node++) {
        int g = batch[node];
        if (g != curg) {
            atomicAdd(&pooled[curg * HC + c], accu);
            accu = 0.0f;
            curg = g;
        }
        accu += h[(size_t)node * HC + c];
    }
    atomicAdd(&pooled[curg * HC + c], accu);
}

__global__ void fc_kernel(const float* __restrict__ pooled, const int* __restrict__ cnt,
                          const float* __restrict__ Wfc, const float* __restrict__ bfc,
                          float* __restrict__ out) {
    int g = blockIdx.x;
    int o = threadIdx.x;  // 64
    __shared__ float pr[HC];
    float invc = 1.0f / fmaxf((float)cnt[g], 1.0f);
    for (int c = o; c < HC; c += 64) pr[c] = pooled[g * HC + c] * invc;
    __syncthreads();
    float accu = bfc[o];
#pragma unroll 8
    for (int c = 0; c < HC; c++) accu += pr[c] * Wfc[c * OUTF + o];
    out[g * OUTF + o] = accu;
}

// ---------------- host orchestration ----------------
extern "C" void kernel_launch(void* const* d_in, const int* in_sizes, int n_in,
                              void* d_out, int out_size) {
    const float* x = (const float*)d_in[0];
    const int* edge = (const int*)d_in[1];   // [2,E]: row0=src, row1=dst
    const int* batch = (const int*)d_in[2];
    const float* Wq0 = (const float*)d_in[3];
    const float* bq0 = (const float*)d_in[4];
    const float* Wk0 = (const float*)d_in[5];
    const float* bk0 = (const float*)d_in[6];
    const float* Wv0 = (const float*)d_in[7];
    const float* bv0 = (const float*)d_in[8];
    const float* Ws0 = (const float*)d_in[9];
    const float* bs0 = (const float*)d_in[10];
    const float* Wq = (const float*)d_in[11];
    const float* bq = (const float*)d_in[12];
    const float* Wk = (const float*)d_in[13];
    const float* bk = (const float*)d_in[14];
    const float* Wv = (const float*)d_in[15];
    const float* bv = (const float*)d_in[16];
    const float* Ws = (const float*)d_in[17];
    const float* bs = (const float*)d_in[18];
    const float* Wfc = (const float*)d_in[19];
    const float* bfc = (const float*)d_in[20];
    float* out = (float*)d_out;

    const int* srcp = edge;
    const int* dstp = edge + EE;

    float *q_p, *skip_p, *h_p, *pooled_p;
    __nv_bfloat16 *kb_p, *vb_p;
    int *deg_p, *rowptr_p, *cursor_p, *csrsrc_p, *gcnt_p;
    cudaGetSymbolAddress((void**)&q_p, g_q);
    cudaGetSymbolAddress((void**)&kb_p, g_kb);
    cudaGetSymbolAddress((void**)&vb_p, g_vb);
    cudaGetSymbolAddress((void**)&skip_p, g_skip);
    cudaGetSymbolAddress((void**)&h_p, g_h);
    cudaGetSymbolAddress((void**)&deg_p, g_deg);
    cudaGetSymbolAddress((void**)&rowptr_p, g_rowptr);
    cudaGetSymbolAddress((void**)&cursor_p, g_cursor);
    cudaGetSymbolAddress((void**)&csrsrc_p, g_csrsrc);
    cudaGetSymbolAddress((void**)&pooled_p, g_pooled);
    cudaGetSymbolAddress((void**)&gcnt_p, g_gcnt);

    // idempotent; no static guards (harness contract forbids them)
    cudaFuncSetAttribute(gemm4_tf32_kernel,
                         cudaFuncAttributeMaxDynamicSharedMemorySize, GEMM_SMEM);

    // ---- CSR build (edges identical across layers; build once) ----
    zero_i_kernel<<<(NN + 255) / 256, 256>>>(deg_p, NN);
    hist_kernel<<<(EE + 255) / 256, 256>>>(dstp, deg_p, EE);
    scan_kernel<<<1, 1024>>>(deg_p, rowptr_p, NN);
    cursor_init_kernel<<<(NN + 255) / 256, 256>>>(rowptr_p, cursor_p, NN);
    scatter_kernel<<<(EE + 255) / 256, 256>>>(srcp, dstp, cursor_p, csrsrc_p, EE);

    dim3 ggrid((NN + BM - 1) / BM, HC / BN, 4);
    int attn_blocks = (NN + 7) / 8;

    // ---- layer 0 (input x, K=128) ----
    {
        GemmPtrs P;
        P.W[0] = Wq0; P.W[1] = Wk0; P.W[2] = Wv0; P.W[3] = Ws0;
        P.b[0] = bq0; P.b[1] = bk0; P.b[2] = bv0; P.b[3] = bs0;
        P.C[0] = q_p; P.C[1] = kb_p; P.C[2] = vb_p; P.C[3] = skip_p;
        P.bf16_mask = 0b0110;
        gemm4_tf32_kernel<<<ggrid, 256, GEMM_SMEM>>>(x, IN_F, P, NN);
        attn_kernel<<<attn_blocks, 256>>>(q_p, kb_p, vb_p, skip_p, rowptr_p, csrsrc_p, h_p, NN);
    }

    // ---- layers 1..3 (input g_h, K=256) ----
    for (int l = 0; l < NLAYERS - 1; l++) {
        GemmPtrs P;
        size_t wo = (size_t)l * HC * HC;
        size_t bo = (size_t)l * HC;
        P.W[0] = Wq + wo; P.W[1] = Wk + wo; P.W[2] = Wv + wo; P.W[3] = Ws + wo;
        P.b[0] = bq + bo; P.b[1] = bk + bo; P.b[2] = bv + bo; P.b[3] = bs + bo;
        P.C[0] = q_p; P.C[1] = kb_p; P.C[2] = vb_p; P.C[3] = skip_p;
        P.bf16_mask = 0b0110;
        gemm4_tf32_kernel<<<ggrid, 256, GEMM_SMEM>>>(h_p, HC, P, NN);
        attn_kernel<<<attn_blocks, 256>>>(q_p, kb_p, vb_p, skip_p, rowptr_p, csrsrc_p, h_p, NN);
    }

    // ---- global mean pool + FC ----
    zero_f_kernel<<<(GG * HC + 255) / 256, 256>>>(pooled_p, GG * HC);
    zero_i_kernel<<<1, 64>>>(gcnt_p, GG);
    pool_cnt_kernel<<<(NN + 255) / 256, 256>>>(batch, gcnt_p, NN);
    pool_sum_kernel<<<(NN + POOL_NODES - 1) / POOL_NODES, 256>>>(h_p, batch, pooled_p, NN);
    fc_kernel<<<GG, OUTF>>>(pooled_p, gcnt_p, Wfc, bfc, out);
}

// round 10
// speedup vs baseline: 2.0045x; 1.0025x over previous
#include <cuda_runtime.h>
#include <cuda_bf16.h>
#include <cstdint>

#define NN 50000
#define EE 800000
#define IN_F 128
#define HC 256
#define NHEAD 8
#define CDIM 32
#define GG 64
#define OUTF 64
#define NLAYERS 4

// ---------------- scratch (device globals; no allocation allowed) ----------------
__device__ float g_q[(size_t)NN * HC];
__device__ __nv_bfloat16 g_kb[(size_t)NN * HC];
__device__ __nv_bfloat16 g_vb[(size_t)NN * HC];
__device__ float g_skip[(size_t)NN * HC];
__device__ float g_h[(size_t)NN * HC];
__device__ int   g_deg[NN];
__device__ int   g_rowptr[NN + 1];
__device__ int   g_cursor[NN];
__device__ int   g_csrsrc[EE];
__device__ float g_pooled[GG * HC];
__device__ int   g_gcnt[GG];

// ---------------- small utility kernels ----------------
__global__ void zero_i_kernel(int* p, int n) {
    int i = blockIdx.x * blockDim.x + threadIdx.x;
    if (i < n) p[i] = 0;
}
__global__ void zero_f_kernel(float* p, int n) {
    int i = blockIdx.x * blockDim.x + threadIdx.x;
    if (i < n) p[i] = 0.0f;
}

// ---------------- CSR build ----------------
__global__ void hist_kernel(const int* __restrict__ dst, int* __restrict__ deg, int e) {
    int i = blockIdx.x * blockDim.x + threadIdx.x;
    if (i < e) atomicAdd(&deg[dst[i]], 1);
}

__global__ void scan_kernel(const int* __restrict__ deg, int* __restrict__ rowptr, int n) {
    __shared__ int sh[1024];
    __shared__ int carry;
    int tid = threadIdx.x;
    if (tid == 0) { carry = 0; rowptr[0] = 0; }
    __syncthreads();
    for (int base = 0; base < n; base += 1024) {
        int i = base + tid;
        sh[tid] = (i < n) ? deg[i] : 0;
        __syncthreads();
        for (int off = 1; off < 1024; off <<= 1) {
            int t = (tid >= off) ? sh[tid - off] : 0;
            __syncthreads();
            sh[tid] += t;
            __syncthreads();
        }
        int c = carry;
        if (i < n) rowptr[i + 1] = sh[tid] + c;
        __syncthreads();
        if (tid == 0) carry = c + sh[1023];
        __syncthreads();
    }
}

__global__ void cursor_init_kernel(const int* __restrict__ rowptr, int* __restrict__ cur, int n) {
    int i = blockIdx.x * blockDim.x + threadIdx.x;
    if (i < n) cur[i] = rowptr[i];
}

__global__ void scatter_kernel(const int* __restrict__ src, const int* __restrict__ dst,
                               int* __restrict__ cur, int* __restrict__ csrsrc, int e) {
    int i = blockIdx.x * blockDim.x + threadIdx.x;
    if (i < e) {
        int d = dst[i];
        int pos = atomicAdd(&cur[d], 1);
        csrsrc[pos] = src[i];
    }
}

// ---------------- tf32 tensor-core GEMM, smem double-buffered ----------------
struct GemmPtrs {
    const float* W[4];
    const float* b[4];
    void* C[4];
    int bf16_mask;
};

#define BM 128
#define BN 128
#define BK 32
#define APITCH 136
#define BPITCH 136
#define ASZ (BK * APITCH)
#define BSZ (BK * BPITCH)
#define GEMM_SMEM (2 * (ASZ + BSZ) * 4)

__device__ __forceinline__ float to_tf32(float x) {
    uint32_t u;
    asm("cvt.rna.tf32.f32 %0, %1;" : "=r"(u) : "f"(x));
    return __uint_as_float(u);
}

__device__ __forceinline__ void mma_tf32(float* d, const uint32_t* a, const uint32_t* b) {
    asm volatile(
        "mma.sync.aligned.m16n8k8.row.col.f32.tf32.tf32.f32 "
        "{%0,%1,%2,%3}, {%4,%5,%6,%7}, {%8,%9}, {%0,%1,%2,%3};"
        : "+f"(d[0]), "+f"(d[1]), "+f"(d[2]), "+f"(d[3])
        : "r"(a[0]), "r"(a[1]), "r"(a[2]), "r"(a[3]), "r"(b[0]), "r"(b[1]));
}

__global__ __launch_bounds__(256) void gemm4_tf32_kernel(const float* __restrict__ A, int K,
                                                         GemmPtrs P, int M) {
    const float* __restrict__ W = P.W[blockIdx.z];
    const float* __restrict__ bias = P.b[blockIdx.z];
    bool out_bf16 = (P.bf16_mask >> blockIdx.z) & 1;
    float* __restrict__ Cf = (float*)P.C[blockIdx.z];
    __nv_bfloat16* __restrict__ Cb = (__nv_bfloat16*)P.C[blockIdx.z];

    extern __shared__ float sm[];
    float* AsBase = sm;                 // 2 * ASZ
    float* BsBase = sm + 2 * ASZ;       // 2 * BSZ

    int t = threadIdx.x;
    int wid = t >> 5, lane = t & 31;
    int gid = lane >> 2, tig = lane & 3;
    int warpM = wid & 3;
    int warpN = wid >> 2;
    int m0 = blockIdx.x * BM;
    int n0 = blockIdx.y * BN;

    float acc[2][8][4];
#pragma unroll
    for (int mt = 0; mt < 2; mt++)
#pragma unroll
        for (int nt = 0; nt < 8; nt++)
#pragma unroll
            for (int j = 0; j < 4; j++) acc[mt][nt][j] = 0.0f;

    float4 pa[4], pb[4];
    int ntiles = K / BK;

    // prefetch tile 0 into regs
#pragma unroll
    for (int u = 0; u < 4; u++) {
        int f = t + u * 256;
        int r = f >> 3, c4 = f & 7;
        int gm = m0 + r;
        pa[u] = (gm < M) ? *(const float4*)(A + (size_t)gm * K + c4 * 4)
                         : make_float4(0.f, 0.f, 0.f, 0.f);
        int kr = f >> 5, bc4 = f & 31;
        pb[u] = *(const float4*)(W + (size_t)kr * HC + n0 + bc4 * 4);
    }
    // store tile 0 into buffer 0
#pragma unroll
    for (int u = 0; u < 4; u++) {
        int f = t + u * 256;
        int r = f >> 3, c4 = f & 7;
        AsBase[(c4 * 4 + 0) * APITCH + r] = to_tf32(pa[u].x);
        AsBase[(c4 * 4 + 1) * APITCH + r] = to_tf32(pa[u].y);
        AsBase[(c4 * 4 + 2) * APITCH + r] = to_tf32(pa[u].z);
        AsBase[(c4 * 4 + 3) * APITCH + r] = to_tf32(pa[u].w);
        int kr = f >> 5, bc4 = f & 31;
        BsBase[kr * BPITCH + bc4 * 4 + 0] = to_tf32(pb[u].x);
        BsBase[kr * BPITCH + bc4 * 4 + 1] = to_tf32(pb[u].y);
        BsBase[kr * BPITCH + bc4 * 4 + 2] = to_tf32(pb[u].z);
        BsBase[kr * BPITCH + bc4 * 4 + 3] = to_tf32(pb[u].w);
    }
    __syncthreads();

    for (int tile = 0; tile < ntiles; tile++) {
        int cur = tile & 1;
        const float* As = AsBase + cur * ASZ;
        const float* Bs = BsBase + cur * BSZ;
        bool have_next = (tile + 1 < ntiles);

        // issue global loads for next tile (consumed after the mma section)
        if (have_next) {
            int k0 = (tile + 1) * BK;
#pragma unroll
            for (int u = 0; u < 4; u++) {
                int f = t + u * 256;
                int r = f >> 3, c4 = f & 7;
                int gm = m0 + r;
                pa[u] = (gm < M) ? *(const float4*)(A + (size_t)gm * K + k0 + c4 * 4)
                                 : make_float4(0.f, 0.f, 0.f, 0.f);
                int kr = f >> 5, bc4 = f & 31;
                pb[u] = *(const float4*)(W + (size_t)(k0 + kr) * HC + n0 + bc4 * 4);
            }
        }

#pragma unroll
        for (int ks = 0; ks < 4; ks++) {
            int kb = ks * 8;
            uint32_t a[2][4];
#pragma unroll
            for (int mt = 0; mt < 2; mt++) {
                int m = warpM * 32 + mt * 16 + gid;
                a[mt][0] = __float_as_uint(As[(kb + tig) * APITCH + m]);
                a[mt][1] = __float_as_uint(As[(kb + tig) * APITCH + m + 8]);
                a[mt][2] = __float_as_uint(As[(kb + tig + 4) * APITCH + m]);
                a[mt][3] = __float_as_uint(As[(kb + tig + 4) * APITCH + m + 8]);
            }
            uint32_t b[8][2];
#pragma unroll
            for (int nt = 0; nt < 8; nt++) {
                int n = warpN * 64 + nt * 8 + gid;
                b[nt][0] = __float_as_uint(Bs[(kb + tig) * BPITCH + n]);
                b[nt][1] = __float_as_uint(Bs[(kb + tig + 4) * BPITCH + n]);
            }
#pragma unroll
            for (int mt = 0; mt < 2; mt++)
#pragma unroll
                for (int nt = 0; nt < 8; nt++) mma_tf32(acc[mt][nt], a[mt], b[nt]);
        }

        // store next tile into the other buffer (safe: the last reads of that
        // buffer completed before the barrier that ended the previous iteration)
        if (have_next) {
            float* Asn = AsBase + (cur ^ 1) * ASZ;
            float* Bsn = BsBase + (cur ^ 1) * BSZ;
#pragma unroll
            for (int u = 0; u < 4; u++) {
                int f = t + u * 256;
                int r = f >> 3, c4 = f & 7;
                Asn[(c4 * 4 + 0) * APITCH + r] = to_tf32(pa[u].x);
                Asn[(c4 * 4 + 1) * APITCH + r] = to_tf32(pa[u].y);
                Asn[(c4 * 4 + 2) * APITCH + r] = to_tf32(pa[u].z);
                Asn[(c4 * 4 + 3) * APITCH + r] = to_tf32(pa[u].w);
                int kr = f >> 5, bc4 = f & 31;
                Bsn[kr * BPITCH + bc4 * 4 + 0] = to_tf32(pb[u].x);
                Bsn[kr * BPITCH + bc4 * 4 + 1] = to_tf32(pb[u].y);
                Bsn[kr * BPITCH + bc4 * 4 + 2] = to_tf32(pb[u].z);
                Bsn[kr * BPITCH + bc4 * 4 + 3] = to_tf32(pb[u].w);
            }
        }
        __syncthreads();
    }

    // epilogue
#pragma unroll
    for (int mt = 0; mt < 2; mt++) {
#pragma unroll
        for (int nt = 0; nt < 8; nt++) {
            int n = n0 + warpN * 64 + nt * 8 + tig * 2;
            float b0 = bias[n];
            float b1 = bias[n + 1];
            int row0 = m0 + warpM * 32 + mt * 16 + gid;
            int row1 = row0 + 8;
            float v00 = acc[mt][nt][0] + b0, v01 = acc[mt][nt][1] + b1;
            float v10 = acc[mt][nt][2] + b0, v11 = acc[mt][nt][3] + b1;
            if (out_bf16) {
                if (row0 < M)
                    *(__nv_bfloat162*)(Cb + (size_t)row0 * HC + n) = __floats2bfloat162_rn(v00, v01);
                if (row1 < M)
                    *(__nv_bfloat162*)(Cb + (size_t)row1 * HC + n) = __floats2bfloat162_rn(v10, v11);
            } else {
                if (row0 < M) *(float2*)(Cf + (size_t)row0 * HC + n) = make_float2(v00, v01);
                if (row1 < M) *(float2*)(Cf + (size_t)row1 * HC + n) = make_float2(v10, v11);
            }
        }
    }
}

// ---------------- attention: one warp per dst node, 2-way ILP streaming softmax ----------------
__global__ __launch_bounds__(256) void attn_kernel(
    const float* __restrict__ q, const __nv_bfloat16* __restrict__ kb,
    const __nv_bfloat16* __restrict__ vb, const float* __restrict__ skp,
    const int* __restrict__ rowptr, const int* __restrict__ srcs,
    float* __restrict__ hout, int n_nodes) {

    int warp = (blockIdx.x * blockDim.x + threadIdx.x) >> 5;
    int lane = threadIdx.x & 31;
    if (warp >= n_nodes) return;

    // lane l owns channels [8l, 8l+8) -> head l/4
    const float4* qp = (const float4*)(q + (size_t)warp * HC);
    float4 q1 = qp[lane * 2];
    float4 q2 = qp[lane * 2 + 1];

    const float scale = 0.17677669529663687f;  // 1/sqrt(32)

    // two independent softmax streams (A: even edges, B: odd edges)
    float mA = -1e30f, sA = 0.0f;
    float aA0 = 0.f, aA1 = 0.f, aA2 = 0.f, aA3 = 0.f, aA4 = 0.f, aA5 = 0.f, aA6 = 0.f, aA7 = 0.f;
    float mB = -1e30f, sB = 0.0f;
    float aB0 = 0.f, aB1 = 0.f, aB2 = 0.f, aB3 = 0.f, aB4 = 0.f, aB5 = 0.f, aB6 = 0.f, aB7 = 0.f;

    int e0 = rowptr[warp];
    int e1 = rowptr[warp + 1];

    // current pair + prefetched next pair
    uint4 kA, vA, kB, vB;
    if (e0 < e1) {
        int s = srcs[e0];
        kA = *(const uint4*)(kb + (size_t)s * HC + lane * 8);
        vA = *(const uint4*)(vb + (size_t)s * HC + lane * 8);
        if (e0 + 1 < e1) {
            int s2 = srcs[e0 + 1];
            kB = *(const uint4*)(kb + (size_t)s2 * HC + lane * 8);
            vB = *(const uint4*)(vb + (size_t)s2 * HC + lane * 8);
        }
    }

    for (int e = e0; e < e1; e += 2) {
        uint4 ckA = kA, cvA = vA, ckB = kB, cvB = vB;
        bool haveB = (e + 1 < e1);
        // prefetch next pair (overlaps both dependent chains below)
        if (e + 2 < e1) {
            int sa = srcs[e + 2];
            kA = *(const uint4*)(kb + (size_t)sa * HC + lane * 8);
            vA = *(const uint4*)(vb + (size_t)sa * HC + lane * 8);
            if (e + 3 < e1) {
                int sb = srcs[e + 3];
                kB = *(const uint4*)(kb + (size_t)sb * HC + lane * 8);
                vB = *(const uint4*)(vb + (size_t)sb * HC + lane * 8);
            }
        }

        // ---- stream A ----
        {
            float2 k0 = __bfloat1622float2(*(__nv_bfloat162*)&ckA.x);
            float2 k1 = __bfloat1622float2(*(__nv_bfloat162*)&ckA.y);
            float2 k2 = __bfloat1622float2(*(__nv_bfloat162*)&ckA.z);
            float2 k3 = __bfloat1622float2(*(__nv_bfloat162*)&ckA.w);
            float d = q1.x * k0.x + q1.y * k0.y + q1.z * k1.x + q1.w * k1.y +
                      q2.x * k2.x + q2.y * k2.y + q2.z * k3.x + q2.w * k3.y;
            d += __shfl_xor_sync(0xffffffffu, d, 1);
            d += __shfl_xor_sync(0xffffffffu, d, 2);
            float logit = d * scale;
            float mn = fmaxf(mA, logit);
            float corr = __expf(mA - mn);
            float p = __expf(logit - mn);
            mA = mn;
            sA = sA * corr + p;
            float2 v0 = __bfloat1622float2(*(__nv_bfloat162*)&cvA.x);
            float2 v1 = __bfloat1622float2(*(__nv_bfloat162*)&cvA.y);
            float2 v2 = __bfloat1622float2(*(__nv_bfloat162*)&cvA.z);
            float2 v3 = __bfloat1622float2(*(__nv_bfloat162*)&cvA.w);
            aA0 = aA0 * corr + p * v0.x;
            aA1 = aA1 * corr + p * v0.y;
            aA2 = aA2 * corr + p * v1.x;
            aA3 = aA3 * corr + p * v1.y;
            aA4 = aA4 * corr + p * v2.x;
            aA5 = aA5 * corr + p * v2.y;
            aA6 = aA6 * corr + p * v3.x;
            aA7 = aA7 * corr + p * v3.y;
        }
        // ---- stream B ----
        if (haveB) {
            float2 k0 = __bfloat1622float2(*(__nv_bfloat162*)&ckB.x);
            float2 k1 = __bfloat1622float2(*(__nv_bfloat162*)&ckB.y);
            float2 k2 = __bfloat1622float2(*(__nv_bfloat162*)&ckB.z);
            float2 k3 = __bfloat1622float2(*(__nv_bfloat162*)&ckB.w);
            float d = q1.x * k0.x + q1.y * k0.y + q1.z * k1.x + q1.w * k1.y +
                      q2.x * k2.x + q2.y * k2.y + q2.z * k3.x + q2.w * k3.y;
            d += __shfl_xor_sync(0xffffffffu, d, 1);
            d += __shfl_xor_sync(0xffffffffu, d, 2);
            float logit = d * scale;
            float mn = fmaxf(mB, logit);
            float corr = __expf(mB - mn);
            float p = __expf(logit - mn);
            mB = mn;
            sB = sB * corr + p;
            float2 v0 = __bfloat1622float2(*(__nv_bfloat162*)&cvB.x);
            float2 v1 = __bfloat1622float2(*(__nv_bfloat162*)&cvB.y);
            float2 v2 = __bfloat1622float2(*(__nv_bfloat162*)&cvB.z);
            float2 v3 = __bfloat1622float2(*(__nv_bfloat162*)&cvB.w);
            aB0 = aB0 * corr + p * v0.x;
            aB1 = aB1 * corr + p * v0.y;
            aB2 = aB2 * corr + p * v1.x;
            aB3 = aB3 * corr + p * v1.y;
            aB4 = aB4 * corr + p * v2.x;
            aB5 = aB5 * corr + p * v2.y;
            aB6 = aB6 * corr + p * v3.x;
            aB7 = aB7 * corr + p * v3.y;
        }
    }

    // merge streams (exact flash merge; sB=0 if no odd edges so B contributes nothing)
    float mn = fmaxf(mA, mB);
    float cA = __expf(mA - mn);
    float cB = __expf(mB - mn);
    float ssum = sA * cA + sB * cB;
    float acc0 = aA0 * cA + aB0 * cB;
    float acc1 = aA1 * cA + aB1 * cB;
    float acc2 = aA2 * cA + aB2 * cB;
    float acc3 = aA3 * cA + aB3 * cB;
    float acc4 = aA4 * cA + aB4 * cB;
    float acc5 = aA5 * cA + aB5 * cB;
    float acc6 = aA6 * cA + aB6 * cB;
    float acc7 = aA7 * cA + aB7 * cB;

    float inv = 1.0f / (ssum + 1e-16f);
    const float4* sp = (const float4*)(skp + (size_t)warp * HC);
    float4 s1 = sp[lane * 2];
    float4 s2 = sp[lane * 2 + 1];
    float4 o1, o2;
    o1.x = fmaxf(acc0 * inv + s1.x, 0.f);
    o1.y = fmaxf(acc1 * inv + s1.y, 0.f);
    o1.z = fmaxf(acc2 * inv + s1.z, 0.f);
    o1.w = fmaxf(acc3 * inv + s1.w, 0.f);
    o2.x = fmaxf(acc4 * inv + s2.x, 0.f);
    o2.y = fmaxf(acc5 * inv + s2.y, 0.f);
    o2.z = fmaxf(acc6 * inv + s2.z, 0.f);
    o2.w = fmaxf(acc7 * inv + s2.w, 0.f);
    float4* op = (float4*)(hout + (size_t)warp * HC);
    op[lane * 2] = o1;
    op[lane * 2 + 1] = o2;
}

// ---------------- pooling + FC ----------------
__global__ void pool_cnt_kernel(const int* __restrict__ batch, int* __restrict__ cnt, int n) {
    int i = blockIdx.x * blockDim.x + threadIdx.x;
    if (i < n) atomicAdd(&cnt[batch[i]], 1);
}

#define POOL_NODES 128
__global__ __launch_bounds__(256) void pool_sum_kernel(const float* __restrict__ h,
                                                       const int* __restrict__ batch,
                                                       float* __restrict__ pooled, int n) {
    int c = threadIdx.x;
    int node0 = blockIdx.x * POOL_NODES;
    int nodeEnd = min(node0 + POOL_NODES, n);
    int curg = batch[node0];
    float accu = 0.0f;
    for (int node = node0; node < nodeEnd; node++) {
        int g = batch[node];
        if (g != curg) {
            atomicAdd(&pooled[curg * HC + c], accu);
            accu = 0.0f;
            curg = g;
        }
        accu += h[(size_t)node * HC + c];
    }
    atomicAdd(&pooled[curg * HC + c], accu);
}

__global__ void fc_kernel(const float* __restrict__ pooled, const int* __restrict__ cnt,
                          const float* __restrict__ Wfc, const float* __restrict__ bfc,
                          float* __restrict__ out) {
    int g = blockIdx.x;
    int o = threadIdx.x;  // 64
    __shared__ float pr[HC];
    float invc = 1.0f / fmaxf((float)cnt[g], 1.0f);
    for (int c = o; c < HC; c += 64) pr[c] = pooled[g * HC + c] * invc;
    __syncthreads();
    float accu = bfc[o];
#pragma unroll 8
    for (int c = 0; c < HC; c++) accu += pr[c] * Wfc[c * OUTF + o];
    out[g * OUTF + o] = accu;
}

// ---------------- host orchestration ----------------
extern "C" void kernel_launch(void* const* d_in, const int* in_sizes, int n_in,
                              void* d_out, int out_size) {
    const float* x = (const float*)d_in[0];
    const int* edge = (const int*)d_in[1];   // [2,E]: row0=src, row1=dst
    const int* batch = (const int*)d_in[2];
    const float* Wq0 = (const float*)d_in[3];
    const float* bq0 = (const float*)d_in[4];
    const float* Wk0 = (const float*)d_in[5];
    const float* bk0 = (const float*)d_in[6];
    const float* Wv0 = (const float*)d_in[7];
    const float* bv0 = (const float*)d_in[8];
    const float* Ws0 = (const float*)d_in[9];
    const float* bs0 = (const float*)d_in[10];
    const float* Wq = (const float*)d_in[11];
    const float* bq = (const float*)d_in[12];
    const float* Wk = (const float*)d_in[13];
    const float* bk = (const float*)d_in[14];
    const float* Wv = (const float*)d_in[15];
    const float* bv = (const float*)d_in[16];
    const float* Ws = (const float*)d_in[17];
    const float* bs = (const float*)d_in[18];
    const float* Wfc = (const float*)d_in[19];
    const float* bfc = (const float*)d_in[20];
    float* out = (float*)d_out;

    const int* srcp = edge;
    const int* dstp = edge + EE;

    float *q_p, *skip_p, *h_p, *pooled_p;
    __nv_bfloat16 *kb_p, *vb_p;
    int *deg_p, *rowptr_p, *cursor_p, *csrsrc_p, *gcnt_p;
    cudaGetSymbolAddress((void**)&q_p, g_q);
    cudaGetSymbolAddress((void**)&kb_p, g_kb);
    cudaGetSymbolAddress((void**)&vb_p, g_vb);
    cudaGetSymbolAddress((void**)&skip_p, g_skip);
    cudaGetSymbolAddress((void**)&h_p, g_h);
    cudaGetSymbolAddress((void**)&deg_p, g_deg);
    cudaGetSymbolAddress((void**)&rowptr_p, g_rowptr);
    cudaGetSymbolAddress((void**)&cursor_p, g_cursor);
    cudaGetSymbolAddress((void**)&csrsrc_p, g_csrsrc);
    cudaGetSymbolAddress((void**)&pooled_p, g_pooled);
    cudaGetSymbolAddress((void**)&gcnt_p, g_gcnt);

    // idempotent; no static guards (harness contract forbids them)
    cudaFuncSetAttribute(gemm4_tf32_kernel,
                         cudaFuncAttributeMaxDynamicSharedMemorySize, GEMM_SMEM);

    // ---- CSR build (edges identical across layers; build once) ----
    zero_i_kernel<<<(NN + 255) / 256, 256>>>(deg_p, NN);
    hist_kernel<<<(EE + 255) / 256, 256>>>(dstp, deg_p, EE);
    scan_kernel<<<1, 1024>>>(deg_p, rowptr_p, NN);
    cursor_init_kernel<<<(NN + 255) / 256, 256>>>(rowptr_p, cursor_p, NN);
    scatter_kernel<<<(EE + 255) / 256, 256>>>(srcp, dstp, cursor_p, csrsrc_p, EE);

    dim3 ggrid((NN + BM - 1) / BM, HC / BN, 4);
    int attn_blocks = (NN + 7) / 8;

    // ---- layer 0 (input x, K=128) ----
    {
        GemmPtrs P;
        P.W[0] = Wq0; P.W[1] = Wk0; P.W[2] = Wv0; P.W[3] = Ws0;
        P.b[0] = bq0; P.b[1] = bk0; P.b[2] = bv0; P.b[3] = bs0;
        P.C[0] = q_p; P.C[1] = kb_p; P.C[2] = vb_p; P.C[3] = skip_p;
        P.bf16_mask = 0b0110;
        gemm4_tf32_kernel<<<ggrid, 256, GEMM_SMEM>>>(x, IN_F, P, NN);
        attn_kernel<<<attn_blocks, 256>>>(q_p, kb_p, vb_p, skip_p, rowptr_p, csrsrc_p, h_p, NN);
    }

    // ---- layers 1..3 (input g_h, K=256) ----
    for (int l = 0; l < NLAYERS - 1; l++) {
        GemmPtrs P;
        size_t wo = (size_t)l * HC * HC;
        size_t bo = (size_t)l * HC;
        P.W[0] = Wq + wo; P.W[1] = Wk + wo; P.W[2] = Wv + wo; P.W[3] = Ws + wo;
        P.b[0] = bq + bo; P.b[1] = bk + bo; P.b[2] = bv + bo; P.b[3] = bs + bo;
        P.C[0] = q_p; P.C[1] = kb_p; P.C[2] = vb_p; P.C[3] = skip_p;
        P.bf16_mask = 0b0110;
        gemm4_tf32_kernel<<<ggrid, 256, GEMM_SMEM>>>(h_p, HC, P, NN);
        attn_kernel<<<attn_blocks, 256>>>(q_p, kb_p, vb_p, skip_p, rowptr_p, csrsrc_p, h_p, NN);
    }

    // ---- global mean pool + FC ----
    zero_f_kernel<<<(GG * HC + 255) / 256, 256>>>(pooled_p, GG * HC);
    zero_i_kernel<<<1, 64>>>(gcnt_p, GG);
    pool_cnt_kernel<<<(NN + 255) / 256, 256>>>(batch, gcnt_p, NN);
    pool_sum_kernel<<<(NN + POOL_NODES - 1) / POOL_NODES, 256>>>(h_p, batch, pooled_p, NN);
    fc_kernel<<<GG, OUTF>>>(pooled_p, gcnt_p, Wfc, bfc, out);
}